// round 9
// baseline (speedup 1.0000x reference)
#include <cuda_runtime.h>
#include <cuda_bf16.h>
#include <cstdint>
#include <math.h>

#define NTOK   2048
#define ECFG   768
#define SCFG   1024
#define HCFG   12
#define DCFG   64
#define BHCFG  24
#define QMCFG  3072
#define H1C    771
#define SLICESZ ((size_t)NTOK * 768)

typedef unsigned short u16;

// ---------------- scratch: hi/lo bf16 planes ----------------
__device__ __align__(16) u16 g_h_hi [NTOK * ECFG];
__device__ __align__(16) u16 g_h_lo [NTOK * ECFG];
__device__ __align__(16) u16 g_wq_hi[(size_t)2304 * ECFG];
__device__ __align__(16) u16 g_wq_lo[(size_t)2304 * ECFG];
__device__ float g_bqkv[2304];
__device__ __align__(16) u16 g_q_hi [BHCFG * SCFG * DCFG];
__device__ __align__(16) u16 g_q_lo [BHCFG * SCFG * DCFG];
__device__ __align__(16) u16 g_k_hi [BHCFG * SCFG * DCFG];
__device__ __align__(16) u16 g_k_lo [BHCFG * SCFG * DCFG];
__device__ __align__(16) u16 g_vt_hi[BHCFG * DCFG * SCFG];
__device__ __align__(16) u16 g_vt_lo[BHCFG * DCFG * SCFG];
__device__ float g_qn[BHCFG * SCFG];
__device__ float g_kn[BHCFG * SCFG];
__device__ float g_P [(size_t)BHCFG * SCFG * SCFG];
__device__ __align__(16) u16 g_P_hi[(size_t)BHCFG * SCFG * SCFG];
__device__ __align__(16) u16 g_P_lo[(size_t)BHCFG * SCFG * SCFG];
__device__ __align__(16) u16 g_va_hi[NTOK * ECFG];
__device__ __align__(16) u16 g_va_lo[NTOK * ECFG];
__device__ __align__(16) u16 g_wo_hi[(size_t)ECFG * ECFG];
__device__ __align__(16) u16 g_wo_lo[(size_t)ECFG * ECFG];
__device__ float g_x1[NTOK * ECFG];
__device__ __align__(16) u16 g_y_hi [NTOK * ECFG];
__device__ __align__(16) u16 g_y_lo [NTOK * ECFG];
__device__ __align__(16) u16 g_w1_hi[(size_t)896 * ECFG];
__device__ __align__(16) u16 g_w1_lo[(size_t)896 * ECFG];
__device__ __align__(16) u16 g_h1s_hi[4 * SLICESZ];
__device__ __align__(16) u16 g_h1s_lo[4 * SLICESZ];
__device__ __align__(16) u16 g_wv_hi[(size_t)ECFG * ECFG];
__device__ __align__(16) u16 g_wv_lo[(size_t)ECFG * ECFG];
__device__ __align__(16) u16 g_z_hi [(size_t)NTOK * QMCFG];
__device__ __align__(16) u16 g_z_lo [(size_t)NTOK * QMCFG];
__device__ __align__(16) u16 g_w2_hi[(size_t)ECFG * QMCFG];
__device__ __align__(16) u16 g_w2_lo[(size_t)ECFG * QMCFG];

// ---------------- helpers ----------------
__device__ __forceinline__ uint32_t smem_u32(const void* p) {
    uint32_t a;
    asm("{ .reg .u64 t; cvta.to.shared.u64 t, %1; cvt.u32.u64 %0, t; }" : "=r"(a) : "l"(p));
    return a;
}
__device__ __forceinline__ void splitHL(float x, u16& h, u16& l) {
    __nv_bfloat16 bh = __float2bfloat16(x);
    __nv_bfloat16 bl = __float2bfloat16(x - __bfloat162float(bh));
    h = __bfloat16_as_ushort(bh);
    l = __bfloat16_as_ushort(bl);
}
__device__ __forceinline__ float joinHL(u16 h, u16 l) {
    return __bfloat162float(__ushort_as_bfloat16(h)) + __bfloat162float(__ushort_as_bfloat16(l));
}
__device__ __forceinline__ void ldsm4(uint32_t* r, uint32_t addr) {
    asm volatile("ldmatrix.sync.aligned.m8n8.x4.shared.b16 {%0,%1,%2,%3}, [%4];"
        : "=r"(r[0]), "=r"(r[1]), "=r"(r[2]), "=r"(r[3]) : "r"(addr));
}
__device__ __forceinline__ void mma16816(float* c, const uint32_t* a, const uint32_t* b) {
    asm volatile("mma.sync.aligned.m16n8k16.row.col.f32.bf16.bf16.f32 "
        "{%0,%1,%2,%3}, {%4,%5,%6,%7}, {%8,%9}, {%0,%1,%2,%3};"
        : "+f"(c[0]), "+f"(c[1]), "+f"(c[2]), "+f"(c[3])
        : "r"(a[0]), "r"(a[1]), "r"(a[2]), "r"(a[3]), "r"(b[0]), "r"(b[1]));
}
__device__ __forceinline__ void cp16(uint32_t dst, const void* src) {
    asm volatile("cp.async.cg.shared.global [%0], [%1], 16;" :: "r"(dst), "l"(src));
}
#define CP_COMMIT() asm volatile("cp.async.commit_group;" ::: "memory")
#define CP_WAIT1()  asm volatile("cp.async.wait_group 1;" ::: "memory")
#define CP_WAIT0()  asm volatile("cp.async.wait_group 0;" ::: "memory")

// ---------------- fused weight conversion ----------------
__global__ void __launch_bounds__(256) convAll(
    const float* __restrict__ Wq, const float* __restrict__ Wk, const float* __restrict__ Wv,
    const float* __restrict__ Wo, const float* __restrict__ W1, const float* __restrict__ Wvq,
    const float* __restrict__ W2)
{
    const int job = blockIdx.z;
    const int r = blockIdx.y;
    const int k0 = blockIdx.x * 256 + threadIdx.x;
    const float* src; u16 *dh, *dl;
    int Kc = 768, rows = 768, inRows = 768;
    switch (job) {
        case 0: src = Wq;  dh = g_wq_hi;                      dl = g_wq_lo;                      break;
        case 1: src = Wk;  dh = g_wq_hi + (size_t)768 * 768;  dl = g_wq_lo + (size_t)768 * 768;  break;
        case 2: src = Wv;  dh = g_wq_hi + (size_t)1536 * 768; dl = g_wq_lo + (size_t)1536 * 768; break;
        case 3: src = Wo;  dh = g_wo_hi; dl = g_wo_lo; break;
        case 4: src = W1;  dh = g_w1_hi; dl = g_w1_lo; rows = 896; inRows = H1C; break;
        case 5: src = Wvq; dh = g_wv_hi; dl = g_wv_lo; break;
        default: src = W2; dh = g_w2_hi; dl = g_w2_lo; Kc = 3072; break;
    }
    if (r >= rows || k0 >= 768) return;
#pragma unroll 4
    for (int j = 0; j < 4; ++j) {
        const int k = k0 + j * 768;
        if (k >= Kc) break;
        float v = (r < inRows) ? src[(size_t)r * Kc + k] : 0.f;
        u16 h, l; splitHL(v, h, l);
        dh[(size_t)r * Kc + k] = h;
        dl[(size_t)r * Kc + k] = l;
    }
}

__global__ void bcat_kernel(const float* __restrict__ a, const float* __restrict__ b,
                            const float* __restrict__ c, float* __restrict__ o) {
    int t = blockIdx.x * 256 + threadIdx.x;
    if (t < 768) o[t] = a[t];
    else if (t < 1536) o[t] = b[t - 768];
    else if (t < 2304) o[t] = c[t - 1536];
}

// ---------------- block reductions ----------------
__device__ __forceinline__ float bred_sum(float v, float* sbuf) {
#pragma unroll
    for (int o = 16; o > 0; o >>= 1) v += __shfl_xor_sync(0xffffffffu, v, o);
    int w = threadIdx.x >> 5, l = threadIdx.x & 31;
    __syncthreads();
    if (l == 0) sbuf[w] = v;
    __syncthreads();
    if (threadIdx.x < 32) {
        float t = (l < 8) ? sbuf[l] : 0.f;
#pragma unroll
        for (int o = 4; o > 0; o >>= 1) t += __shfl_xor_sync(0xffffffffu, t, o);
        if (l == 0) sbuf[32] = t;
    }
    __syncthreads();
    return sbuf[32];
}
__device__ __forceinline__ float bred_max(float v, float* sbuf) {
#pragma unroll
    for (int o = 16; o > 0; o >>= 1) v = fmaxf(v, __shfl_xor_sync(0xffffffffu, v, o));
    int w = threadIdx.x >> 5, l = threadIdx.x & 31;
    __syncthreads();
    if (l == 0) sbuf[w] = v;
    __syncthreads();
    if (threadIdx.x < 32) {
        float t = (l < 8) ? sbuf[l] : -1e30f;
#pragma unroll
        for (int o = 4; o > 0; o >>= 1) t = fmaxf(t, __shfl_xor_sync(0xffffffffu, t, o));
        if (l == 0) sbuf[32] = t;
    }
    __syncthreads();
    return sbuf[32];
}

// ---------------- layernorm -> hi/lo planes ----------------
__global__ void __launch_bounds__(256) ln_split(const float* __restrict__ x,
                                                const float* __restrict__ w,
                                                const float* __restrict__ b,
                                                u16* __restrict__ oh, u16* __restrict__ ol) {
    __shared__ float sbuf[34];
    const int row = blockIdx.x;
    const float* xr = x + (size_t)row * ECFG;
    float v[3];
    float s = 0.f, sq = 0.f;
#pragma unroll
    for (int u = 0; u < 3; ++u) {
        v[u] = xr[threadIdx.x + u * 256];
        s += v[u];
        sq += v[u] * v[u];
    }
    s  = bred_sum(s, sbuf);
    sq = bred_sum(sq, sbuf);
    const float mean = s * (1.0f / ECFG);
    const float inv  = rsqrtf(sq * (1.0f / ECFG) - mean * mean + 1e-5f);
#pragma unroll
    for (int u = 0; u < 3; ++u) {
        int e = threadIdx.x + u * 256;
        u16 h, l; splitHL((v[u] - mean) * inv * w[e] + b[e], h, l);
        oh[(size_t)row * ECFG + e] = h;
        ol[(size_t)row * ECFG + e] = l;
    }
}

// ================= HMMA GEMM, 3-term split, 3-stage cp.async pipeline =================
// seg0: Ah.Bh  seg1: Al.Bh  seg2: Ah.Bl
// mode 0: C0 = acc + bias (+resid), fp32
// mode 1: QKV -> q planes Q0, k planes Q1 [bh][s][d]; v transposed planes Q2 [bh][d][s]
// mode 2: vqc: A = slice qi of h1s; +bias, GELU -> z planes [gr*3072+gc*4+qi]
// mode 3: fc1: +bias -> 4 shifted h1 slices, gc < colLimit
// mode 4: logits: A,B offset z*65536, C0 offset z<<20, raw fp32
#define HM_STAGE 18432
#define HM_SMEM  (6 * HM_STAGE)       // 3 stages x (A,B)
__global__ void __launch_bounds__(256, 2) hm3(
    const u16* __restrict__ Ahi, const u16* __restrict__ Alo, int ldA,
    const u16* __restrict__ Bhi, const u16* __restrict__ Blo, int ldB,
    const float* __restrict__ bias, const float* __restrict__ resid,
    float* __restrict__ C0, int ldc,
    u16* __restrict__ Q0h, u16* __restrict__ Q0l,
    u16* __restrict__ Q1h, u16* __restrict__ Q1l,
    u16* __restrict__ Q2h, u16* __restrict__ Q2l,
    int Kc, int mode, int colLimit)
{
    extern __shared__ __align__(16) u16 sm[];
    const int t = threadIdx.x, lane = t & 31, wid = t >> 5;
    const int rowBase = blockIdx.y * 128, colBase = blockIdx.x * 128, qi = blockIdx.z;
    if (mode == 2) { Ahi += (size_t)qi * SLICESZ; Alo += (size_t)qi * SLICESZ; }
    if (mode == 4) {
        Ahi += (size_t)qi << 16; Alo += (size_t)qi << 16;
        Bhi += (size_t)qi << 16; Blo += (size_t)qi << 16;
        C0  += (size_t)qi << 20;
    }
    const int mBase = (wid >> 2) * 64, nBase = (wid & 3) * 32;
    float acc[4][4][4] = {};

    const int srow = t >> 1, half = t & 1;
    const size_t aRowOff = (size_t)(rowBase + srow) * ldA + half * 32;
    const size_t bRowOff = (size_t)(colBase + srow) * ldB + half * 32;
    const uint32_t smb = smem_u32(sm);
    const uint32_t aBuf[3] = { smb,                smb + 2 * HM_STAGE, smb + 4 * HM_STAGE };
    const uint32_t bBuf[3] = { smb + HM_STAGE,     smb + 3 * HM_STAGE, smb + 5 * HM_STAGE };
    const uint32_t dstOff = (uint32_t)(srow * 72 + half * 32) * 2;

    const int mat = lane >> 3, lr8 = lane & 7;
    const int rOff = (mat & 1) * 8 + lr8;
    const int cByte = (mat >> 1) * 16;

    const int nk = Kc >> 6;
    const int NIT = nk * 3;

#define HM_ISSUE(IT, BUF) do { \
    const int seg_ = (IT) / nk; \
    const int kb_ = ((IT) - seg_ * nk) * 64; \
    const u16* ap_ = (seg_ == 1 ? Alo : Ahi) + aRowOff + kb_; \
    const u16* bp_ = (seg_ == 2 ? Blo : Bhi) + bRowOff + kb_; \
    const uint32_t ad_ = aBuf[BUF] + dstOff; \
    const uint32_t bd_ = bBuf[BUF] + dstOff; \
    _Pragma("unroll") \
    for (int j_ = 0; j_ < 4; ++j_) { cp16(ad_ + j_ * 16, ap_ + j_ * 8); cp16(bd_ + j_ * 16, bp_ + j_ * 8); } \
    CP_COMMIT(); \
} while (0)

#define HM_COMPUTE(BUF) do { \
    _Pragma("unroll") \
    for (int s_ = 0; s_ < 4; ++s_) { \
        uint32_t bf_[4][2]; \
        _Pragma("unroll") \
        for (int bp_ = 0; bp_ < 2; ++bp_) { \
            uint32_t r4_[4]; \
            ldsm4(r4_, bBuf[BUF] + (uint32_t)((nBase + bp_ * 16 + rOff) * 144 + cByte + s_ * 32)); \
            bf_[2 * bp_][0] = r4_[0]; bf_[2 * bp_ + 1][0] = r4_[1]; \
            bf_[2 * bp_][1] = r4_[2]; bf_[2 * bp_ + 1][1] = r4_[3]; } \
        _Pragma("unroll") \
        for (int a_ = 0; a_ < 4; ++a_) { \
            uint32_t af_[4]; \
            ldsm4(af_, aBuf[BUF] + (uint32_t)((mBase + a_ * 16 + rOff) * 144 + cByte + s_ * 32)); \
            _Pragma("unroll") \
            for (int bn_ = 0; bn_ < 4; ++bn_) mma16816(acc[a_][bn_], af_, bf_[bn_]); } } \
} while (0)

    HM_ISSUE(0, 0);
    HM_ISSUE(1, 1);
    int buf = 0;
    for (int it = 0; it < NIT; ++it) {
        if (it + 2 < NIT) CP_WAIT1(); else CP_WAIT0();
        __syncthreads();
        if (it + 2 < NIT) {
            int nb = buf + 2; if (nb >= 3) nb -= 3;
            HM_ISSUE(it + 2, nb);
        }
        HM_COMPUTE(buf);
        if (++buf == 3) buf = 0;
    }

    // ---------------- epilogue ----------------
    const int r = lane >> 2, cp = (lane & 3) * 2;
#pragma unroll
    for (int a = 0; a < 4; ++a) {
#pragma unroll
        for (int bn = 0; bn < 4; ++bn) {
            const float* c = acc[a][bn];
            const int gc = colBase + nBase + bn * 8 + cp;
            const float b0 = bias ? bias[gc] : 0.f;
            const float b1 = bias ? bias[gc + 1] : 0.f;
#pragma unroll
            for (int hh = 0; hh < 2; ++hh) {
                const int gr = rowBase + mBase + a * 16 + r + hh * 8;
                float v0 = c[hh * 2] + b0, v1 = c[hh * 2 + 1] + b1;
                if (mode == 0) {
                    if (resid) {
                        v0 += resid[(size_t)gr * ldc + gc];
                        v1 += resid[(size_t)gr * ldc + gc + 1];
                    }
                    *reinterpret_cast<float2*>(C0 + (size_t)gr * ldc + gc) = make_float2(v0, v1);
                } else if (mode == 4) {
                    *reinterpret_cast<float2*>(C0 + (size_t)gr * ldc + gc) = make_float2(v0, v1);
                } else if (mode == 1) {
                    const int which = (gc >= 1536) ? 2 : (gc >= 768 ? 1 : 0);
                    const int e = gc - which * 768;
                    const int h = e >> 6, d = e & 63;
                    const int bb = gr >> 10, s = gr & 1023;
                    u16 h0, l0, h1, l1;
                    splitHL(v0, h0, l0); splitHL(v1, h1, l1);
                    if (which < 2) {
                        u16* dh = which == 0 ? Q0h : Q1h;
                        u16* dl = which == 0 ? Q0l : Q1l;
                        const size_t base = (((size_t)(bb * HCFG + h)) * SCFG + s) * DCFG + d;
                        dh[base] = h0; dh[base + 1] = h1;
                        dl[base] = l0; dl[base + 1] = l1;
                    } else {
                        const size_t base = ((size_t)(bb * HCFG + h)) * DCFG * SCFG + (size_t)d * SCFG + s;
                        Q2h[base] = h0; Q2h[base + SCFG] = h1;
                        Q2l[base] = l0; Q2l[base + SCFG] = l1;
                    }
                } else if (mode == 2) {
                    const float g0 = 0.5f * v0 * (1.0f + erff(v0 * 0.70710678118654752f));
                    const float g1 = 0.5f * v1 * (1.0f + erff(v1 * 0.70710678118654752f));
                    u16 h0, l0, h1, l1;
                    splitHL(g0, h0, l0); splitHL(g1, h1, l1);
                    const size_t base = (size_t)gr * QMCFG + (size_t)gc * 4 + qi;
                    Q0h[base] = h0; Q0h[base + 4] = h1;
                    Q0l[base] = l0; Q0l[base + 4] = l1;
                } else {
                    u16 h0, l0, h1, l1;
                    splitHL(v0, h0, l0); splitHL(v1, h1, l1);
#pragma unroll
                    for (int qq = 0; qq < 4; ++qq) {
                        const int c0 = gc - qq, c1 = gc + 1 - qq;
                        const size_t sb = (size_t)qq * SLICESZ + (size_t)gr * 768;
                        if (c0 >= 0 && c0 < 768 && gc < colLimit)     { Q0h[sb + c0] = h0; Q0l[sb + c0] = l0; }
                        if (c1 >= 0 && c1 < 768 && gc + 1 < colLimit) { Q0h[sb + c1] = h1; Q0l[sb + c1] = l1; }
                    }
                }
            }
        }
    }
}

// ================= PV HMMA, 3-term split, 3-stage pipeline =================
#define PV_STAGE_A 18432
#define PV_STAGE_B 9216
#define PV_SMEM (3 * (PV_STAGE_A + PV_STAGE_B))
__global__ void __launch_bounds__(256, 2) pv3(
    const u16* __restrict__ Phi, const u16* __restrict__ Plo,
    const u16* __restrict__ Vhi, const u16* __restrict__ Vlo,
    u16* __restrict__ vh, u16* __restrict__ vl)
{
    extern __shared__ __align__(16) u16 sm[];
    const int t = threadIdx.x, lane = t & 31, wid = t >> 5;
    const int bh = blockIdx.y;
    const int rowBase = blockIdx.x * 128;
    const u16* Ahi = Phi + ((size_t)bh << 20);
    const u16* Alo = Plo + ((size_t)bh << 20);
    const u16* Bhi = Vhi + (size_t)bh * DCFG * SCFG;
    const u16* Blo = Vlo + (size_t)bh * DCFG * SCFG;
    const int mBase = (wid >> 1) * 32, nBase = (wid & 1) * 32;
    float acc[2][4][4] = {};

    const int srow = t >> 1, half = t & 1;
    const size_t aRowOff = (size_t)(rowBase + srow) * SCFG + half * 32;
    const int srowB = (t & 127) >> 1;
    const size_t bRowOff = (size_t)srowB * SCFG + half * 32;
    const bool doB = t < 128;

    const uint32_t smb = smem_u32(sm);
    const uint32_t aBuf[3] = { smb, smb + PV_STAGE_A + PV_STAGE_B, smb + 2 * (PV_STAGE_A + PV_STAGE_B) };
    const uint32_t bBuf[3] = { aBuf[0] + PV_STAGE_A, aBuf[1] + PV_STAGE_A, aBuf[2] + PV_STAGE_A };
    const uint32_t dstOffA = (uint32_t)(srow * 72 + half * 32) * 2;
    const uint32_t dstOffB = (uint32_t)(srowB * 72 + half * 32) * 2;

    const int mat = lane >> 3, lr8 = lane & 7;
    const int rOff = (mat & 1) * 8 + lr8;
    const int cByte = (mat >> 1) * 16;

    const int nk = SCFG >> 6;
    const int NIT = nk * 3;

#define PV_ISSUE(IT, BUF) do { \
    const int seg_ = (IT) / nk; \
    const int kb_ = ((IT) - seg_ * nk) * 64; \
    const u16* ap_ = (seg_ == 1 ? Alo : Ahi) + aRowOff + kb_; \
    const uint32_t ad_ = aBuf[BUF] + dstOffA; \
    _Pragma("unroll") \
    for (int j_ = 0; j_ < 4; ++j_) cp16(ad_ + j_ * 16, ap_ + j_ * 8); \
    if (doB) { \
        const u16* bp_ = (seg_ == 2 ? Blo : Bhi) + bRowOff + kb_; \
        const uint32_t bd_ = bBuf[BUF] + dstOffB; \
        _Pragma("unroll") \
        for (int j_ = 0; j_ < 4; ++j_) cp16(bd_ + j_ * 16, bp_ + j_ * 8); } \
    CP_COMMIT(); \
} while (0)

#define PV_COMPUTE(BUF) do { \
    _Pragma("unroll") \
    for (int s_ = 0; s_ < 4; ++s_) { \
        uint32_t bf_[4][2]; \
        _Pragma("unroll") \
        for (int bp_ = 0; bp_ < 2; ++bp_) { \
            uint32_t r4_[4]; \
            ldsm4(r4_, bBuf[BUF] + (uint32_t)((nBase + bp_ * 16 + rOff) * 144 + cByte + s_ * 32)); \
            bf_[2 * bp_][0] = r4_[0]; bf_[2 * bp_ + 1][0] = r4_[1]; \
            bf_[2 * bp_][1] = r4_[2]; bf_[2 * bp_ + 1][1] = r4_[3]; } \
        _Pragma("unroll") \
        for (int a_ = 0; a_ < 2; ++a_) { \
            uint32_t af_[4]; \
            ldsm4(af_, aBuf[BUF] + (uint32_t)((mBase + a_ * 16 + rOff) * 144 + cByte + s_ * 32)); \
            _Pragma("unroll") \
            for (int bn_ = 0; bn_ < 4; ++bn_) mma16816(acc[a_][bn_], af_, bf_[bn_]); } } \
} while (0)

    PV_ISSUE(0, 0);
    PV_ISSUE(1, 1);
    int buf = 0;
    for (int it = 0; it < NIT; ++it) {
        if (it + 2 < NIT) CP_WAIT1(); else CP_WAIT0();
        __syncthreads();
        if (it + 2 < NIT) {
            int nb = buf + 2; if (nb >= 3) nb -= 3;
            PV_ISSUE(it + 2, nb);
        }
        PV_COMPUTE(buf);
        if (++buf == 3) buf = 0;
    }

    const int b = bh / HCFG, h = bh % HCFG;
    const int r = lane >> 2, cp = (lane & 3) * 2;
#pragma unroll
    for (int a = 0; a < 2; ++a) {
#pragma unroll
        for (int bn = 0; bn < 4; ++bn) {
            const float* c = acc[a][bn];
            const int d = nBase + bn * 8 + cp;
#pragma unroll
            for (int hh = 0; hh < 2; ++hh) {
                const int s = rowBase + mBase + a * 16 + r + hh * 8;
                const size_t base = ((size_t)(b * SCFG + s)) * ECFG + h * DCFG + d;
                u16 h0, l0, h1, l1;
                splitHL(c[hh * 2], h0, l0); splitHL(c[hh * 2 + 1], h1, l1);
                vh[base] = h0; vh[base + 1] = h1;
                vl[base] = l0; vl[base + 1] = l1;
            }
        }
    }
}

// ---------------- row norms from planes ----------------
__global__ void norm_planes(const u16* __restrict__ sh, const u16* __restrict__ sl,
                            float* __restrict__ dst, int nrows) {
    const int r = blockIdx.x * blockDim.x + threadIdx.x;
    if (r >= nrows) return;
    const uint4* ph = reinterpret_cast<const uint4*>(sh + (size_t)r * DCFG);
    const uint4* pl = reinterpret_cast<const uint4*>(sl + (size_t)r * DCFG);
    float s = 0.f;
#pragma unroll
    for (int i = 0; i < 8; ++i) {
        uint4 th = ph[i], tl = pl[i];
        const uint32_t* wh = &th.x;
        const uint32_t* wl = &tl.x;
#pragma unroll
        for (int j = 0; j < 4; ++j) {
            float a = joinHL((u16)(wh[j] & 0xffffu), (u16)(wl[j] & 0xffffu));
            float b = joinHL((u16)(wh[j] >> 16),     (u16)(wl[j] >> 16));
            s += a * a + b * b;
        }
    }
    dst[r] = s;
}

// ---------------- softmax + RBF mix ----------------
__global__ void __launch_bounds__(256) mix_kernel(const float* __restrict__ P,
                                                  u16* __restrict__ Ph, u16* __restrict__ Pl,
                                                  const float* __restrict__ qn_,
                                                  const float* __restrict__ kn_,
                                                  const float* __restrict__ pond) {
    __shared__ float sbuf[34];
    const int row = blockIdx.x;
    const int bh  = row >> 10;
    const float* prow = P + (size_t)row * SCFG;
    const float* knb = kn_ + (size_t)bh * SCFG;
    const int tid = threadIdx.x;
    const float qn = qn_[row];
    const float sigma2 = fminf(fmaxf(qn, 1e-8f), 1e4f);

    float4 dt  = *reinterpret_cast<const float4*>(prow + tid * 4);
    float4 kn4 = *reinterpret_cast<const float4*>(knb + tid * 4);
    const float d[4]  = {dt.x, dt.y, dt.z, dt.w};
    const float kn[4] = {kn4.x, kn4.y, kn4.z, kn4.w};

    float lm = -1e30f;
#pragma unroll
    for (int u = 0; u < 4; ++u) lm = fmaxf(lm, d[u] * 0.125f);
    const float M = bred_max(lm, sbuf);

    float e[4], rb[4];
    float se = 0.f, sr = 0.f;
#pragma unroll
    for (int u = 0; u < 4; ++u) {
        e[u] = expf(d[u] * 0.125f - M);
        se += e[u];
        const float d2 = fmaxf(qn + kn[u] - 2.f * d[u], 0.f);
        rb[u] = expf(-d2 / sigma2);
        sr += rb[u];
    }
    const float Ls = bred_sum(se, sbuf);
    const float Lr = bred_sum(sr, sbuf);

    const float sv = 1.f / (1.f + expf(-pond[0]));
    const float p0 = 1.f - sv, p1 = sv;
    const float inv = 1.f / (p0 + p1 + 1e-7f);
    const float ca = p0 * inv / Ls;
    const float cb = p1 * inv / fmaxf(Lr, 1e-8f);

    u16 h[4], l[4];
#pragma unroll
    for (int u = 0; u < 4; ++u) splitHL(ca * e[u] + cb * rb[u], h[u], l[u]);
    uint2 ho, lo;
    ho.x = (uint32_t)h[0] | ((uint32_t)h[1] << 16);
    ho.y = (uint32_t)h[2] | ((uint32_t)h[3] << 16);
    lo.x = (uint32_t)l[0] | ((uint32_t)l[1] << 16);
    lo.y = (uint32_t)l[2] | ((uint32_t)l[3] << 16);
    *reinterpret_cast<uint2*>(Ph + (size_t)row * SCFG + tid * 4) = ho;
    *reinterpret_cast<uint2*>(Pl + (size_t)row * SCFG + tid * 4) = lo;
}

// ---------------- launch ----------------
extern "C" void kernel_launch(void* const* d_in, const int* in_sizes, int n_in,
                              void* d_out, int out_size) {
    const float* x     = (const float*)d_in[0];
    const float* ln1_w = (const float*)d_in[1];
    const float* ln1_b = (const float*)d_in[2];
    const float* Wq    = (const float*)d_in[3];
    const float* bq    = (const float*)d_in[4];
    const float* Wk    = (const float*)d_in[5];
    const float* bk    = (const float*)d_in[6];
    const float* Wv    = (const float*)d_in[7];
    const float* bv    = (const float*)d_in[8];
    const float* Wo    = (const float*)d_in[9];
    const float* bo    = (const float*)d_in[10];
    const float* pond  = (const float*)d_in[11];
    const float* ln2_w = (const float*)d_in[12];
    const float* ln2_b = (const float*)d_in[13];
    const float* fc1_W = (const float*)d_in[14];
    const float* fc1_b = (const float*)d_in[15];
    const float* vqc_W = (const float*)d_in[16];
    const float* vqc_b = (const float*)d_in[17];
    const float* fc2_W = (const float*)d_in[18];
    const float* fc2_b = (const float*)d_in[19];
    float* out = (float*)d_out;

    cudaFuncSetAttribute(hm3, cudaFuncAttributeMaxDynamicSharedMemorySize, HM_SMEM);
    cudaFuncSetAttribute(pv3, cudaFuncAttributeMaxDynamicSharedMemorySize, PV_SMEM);

    float *p_bqkv, *p_qn, *p_kn, *p_P, *p_x1;
    u16 *p_h_hi, *p_h_lo, *p_wq_hi, *p_wq_lo, *p_q_hi, *p_q_lo, *p_k_hi, *p_k_lo;
    u16 *p_vt_hi, *p_vt_lo, *p_P_hi, *p_P_lo, *p_va_hi, *p_va_lo, *p_wo_hi, *p_wo_lo;
    u16 *p_y_hi, *p_y_lo, *p_w1_hi, *p_w1_lo, *p_h1s_hi, *p_h1s_lo, *p_wv_hi, *p_wv_lo;
    u16 *p_z_hi, *p_z_lo, *p_w2_hi, *p_w2_lo;
    cudaGetSymbolAddress((void**)&p_bqkv, g_bqkv);
    cudaGetSymbolAddress((void**)&p_qn, g_qn);
    cudaGetSymbolAddress((void**)&p_kn, g_kn);
    cudaGetSymbolAddress((void**)&p_P, g_P);
    cudaGetSymbolAddress((void**)&p_x1, g_x1);
    cudaGetSymbolAddress((void**)&p_h_hi, g_h_hi);     cudaGetSymbolAddress((void**)&p_h_lo, g_h_lo);
    cudaGetSymbolAddress((void**)&p_wq_hi, g_wq_hi);   cudaGetSymbolAddress((void**)&p_wq_lo, g_wq_lo);
    cudaGetSymbolAddress((void**)&p_q_hi, g_q_hi);     cudaGetSymbolAddress((void**)&p_q_lo, g_q_lo);
    cudaGetSymbolAddress((void**)&p_k_hi, g_k_hi);     cudaGetSymbolAddress((void**)&p_k_lo, g_k_lo);
    cudaGetSymbolAddress((void**)&p_vt_hi, g_vt_hi);   cudaGetSymbolAddress((void**)&p_vt_lo, g_vt_lo);
    cudaGetSymbolAddress((void**)&p_P_hi, g_P_hi);     cudaGetSymbolAddress((void**)&p_P_lo, g_P_lo);
    cudaGetSymbolAddress((void**)&p_va_hi, g_va_hi);   cudaGetSymbolAddress((void**)&p_va_lo, g_va_lo);
    cudaGetSymbolAddress((void**)&p_wo_hi, g_wo_hi);   cudaGetSymbolAddress((void**)&p_wo_lo, g_wo_lo);
    cudaGetSymbolAddress((void**)&p_y_hi, g_y_hi);     cudaGetSymbolAddress((void**)&p_y_lo, g_y_lo);
    cudaGetSymbolAddress((void**)&p_w1_hi, g_w1_hi);   cudaGetSymbolAddress((void**)&p_w1_lo, g_w1_lo);
    cudaGetSymbolAddress((void**)&p_h1s_hi, g_h1s_hi); cudaGetSymbolAddress((void**)&p_h1s_lo, g_h1s_lo);
    cudaGetSymbolAddress((void**)&p_wv_hi, g_wv_hi);   cudaGetSymbolAddress((void**)&p_wv_lo, g_wv_lo);
    cudaGetSymbolAddress((void**)&p_z_hi, g_z_hi);     cudaGetSymbolAddress((void**)&p_z_lo, g_z_lo);
    cudaGetSymbolAddress((void**)&p_w2_hi, g_w2_hi);   cudaGetSymbolAddress((void**)&p_w2_lo, g_w2_lo);

    // 0) fused weight conversions + bias concat
    convAll<<<dim3(3, 896, 7), 256>>>(Wq, Wk, Wv, Wo, fc1_W, vqc_W, fc2_W);
    bcat_kernel<<<9, 256>>>(bq, bk, bv, p_bqkv);

    // 1) LN1 -> h planes
    ln_split<<<NTOK, 256>>>(x, ln1_w, ln1_b, p_h_hi, p_h_lo);

    // 2) fused QKV -> q/k planes bhsd, v planes transposed
    hm3<<<dim3(18, 16), 256, HM_SMEM>>>(p_h_hi, p_h_lo, ECFG, p_wq_hi, p_wq_lo, ECFG,
                                        p_bqkv, nullptr, nullptr, 0,
                                        p_q_hi, p_q_lo, p_k_hi, p_k_lo, p_vt_hi, p_vt_lo,
                                        768, 1, 0);

    // 3) norms
    norm_planes<<<(BHCFG * SCFG + 255) / 256, 256>>>(p_q_hi, p_q_lo, p_qn, BHCFG * SCFG);
    norm_planes<<<(BHCFG * SCFG + 255) / 256, 256>>>(p_k_hi, p_k_lo, p_kn, BHCFG * SCFG);

    // 4) logits -> raw dots fp32
    hm3<<<dim3(8, 8, BHCFG), 256, HM_SMEM>>>(p_q_hi, p_q_lo, DCFG, p_k_hi, p_k_lo, DCFG,
                                             nullptr, nullptr, p_P, SCFG,
                                             nullptr, nullptr, nullptr, nullptr, nullptr, nullptr,
                                             64, 4, 0);

    // 5) softmax + RBF -> P planes
    mix_kernel<<<BHCFG * SCFG, 256>>>(p_P, p_P_hi, p_P_lo, p_qn, p_kn, pond);

    // 6) P @ V -> vals planes
    pv3<<<dim3(8, BHCFG), 256, PV_SMEM>>>(p_P_hi, p_P_lo, p_vt_hi, p_vt_lo, p_va_hi, p_va_lo);

    // 7) x1 = x + vals@Wo^T + bo
    hm3<<<dim3(6, 16), 256, HM_SMEM>>>(p_va_hi, p_va_lo, ECFG, p_wo_hi, p_wo_lo, ECFG,
                                       bo, x, p_x1, ECFG,
                                       nullptr, nullptr, nullptr, nullptr, nullptr, nullptr,
                                       768, 0, 0);

    // 8) LN2 -> y planes
    ln_split<<<NTOK, 256>>>(p_x1, ln2_w, ln2_b, p_y_hi, p_y_lo);

    // 9) fc1 -> 4 pre-shifted h1 slices
    hm3<<<dim3(7, 16), 256, HM_SMEM>>>(p_y_hi, p_y_lo, ECFG, p_w1_hi, p_w1_lo, ECFG,
                                       fc1_b, nullptr, nullptr, 0,
                                       p_h1s_hi, p_h1s_lo, nullptr, nullptr, nullptr, nullptr,
                                       768, 3, H1C);

    // 10) vqc + GELU -> z planes (aligned slice per qi)
    hm3<<<dim3(6, 16, 4), 256, HM_SMEM>>>(p_h1s_hi, p_h1s_lo, 768, p_wv_hi, p_wv_lo, ECFG,
                                          vqc_b, nullptr, nullptr, 0,
                                          p_z_hi, p_z_lo, nullptr, nullptr, nullptr, nullptr,
                                          768, 2, 0);

    // 11) out = x1 + z@fc2^T + fc2_b
    hm3<<<dim3(6, 16), 256, HM_SMEM>>>(p_z_hi, p_z_lo, QMCFG, p_w2_hi, p_w2_lo, QMCFG,
                                       fc2_b, p_x1, out, ECFG,
                                       nullptr, nullptr, nullptr, nullptr, nullptr, nullptr,
                                       3072, 0, 0);

    (void)in_sizes; (void)n_in; (void)out_size;
}

// round 10
// speedup vs baseline: 1.0417x; 1.0417x over previous
#include <cuda_runtime.h>
#include <cuda_bf16.h>
#include <cstdint>
#include <math.h>

#define NTOK   2048
#define ECFG   768
#define SCFG   1024
#define HCFG   12
#define DCFG   64
#define BHCFG  24
#define QMCFG  3072
#define H1C    771
#define SLICESZ ((size_t)NTOK * 768)

typedef unsigned short u16;

// ---------------- scratch: hi/lo bf16 planes ----------------
__device__ __align__(16) u16 g_h_hi [NTOK * ECFG];
__device__ __align__(16) u16 g_h_lo [NTOK * ECFG];
__device__ __align__(16) u16 g_wq_hi[(size_t)2304 * ECFG];
__device__ __align__(16) u16 g_wq_lo[(size_t)2304 * ECFG];
__device__ float g_bqkv[2304];
__device__ __align__(16) u16 g_q_hi [BHCFG * SCFG * DCFG];
__device__ __align__(16) u16 g_q_lo [BHCFG * SCFG * DCFG];
__device__ __align__(16) u16 g_k_hi [BHCFG * SCFG * DCFG];
__device__ __align__(16) u16 g_k_lo [BHCFG * SCFG * DCFG];
__device__ __align__(16) u16 g_vt_hi[BHCFG * DCFG * SCFG];
__device__ __align__(16) u16 g_vt_lo[BHCFG * DCFG * SCFG];
__device__ float g_qn[BHCFG * SCFG];
__device__ float g_kn[BHCFG * SCFG];
__device__ float g_P [(size_t)BHCFG * SCFG * SCFG];
__device__ __align__(16) u16 g_P_hi[(size_t)BHCFG * SCFG * SCFG];
__device__ __align__(16) u16 g_P_lo[(size_t)BHCFG * SCFG * SCFG];
__device__ __align__(16) u16 g_va_hi[NTOK * ECFG];
__device__ __align__(16) u16 g_va_lo[NTOK * ECFG];
__device__ __align__(16) u16 g_wo_hi[(size_t)ECFG * ECFG];
__device__ __align__(16) u16 g_wo_lo[(size_t)ECFG * ECFG];
__device__ float g_x1[NTOK * ECFG];
__device__ __align__(16) u16 g_y_hi [NTOK * ECFG];
__device__ __align__(16) u16 g_y_lo [NTOK * ECFG];
__device__ __align__(16) u16 g_w1_hi[(size_t)896 * ECFG];
__device__ __align__(16) u16 g_w1_lo[(size_t)896 * ECFG];
__device__ __align__(16) u16 g_h1s_hi[4 * SLICESZ];
__device__ __align__(16) u16 g_h1s_lo[4 * SLICESZ];
__device__ __align__(16) u16 g_wv_hi[(size_t)ECFG * ECFG];
__device__ __align__(16) u16 g_wv_lo[(size_t)ECFG * ECFG];
__device__ __align__(16) u16 g_z_hi [(size_t)NTOK * QMCFG];
__device__ __align__(16) u16 g_z_lo [(size_t)NTOK * QMCFG];
__device__ __align__(16) u16 g_w2_hi[(size_t)ECFG * QMCFG];
__device__ __align__(16) u16 g_w2_lo[(size_t)ECFG * QMCFG];

// ---------------- helpers ----------------
__device__ __forceinline__ uint32_t smem_u32(const void* p) {
    uint32_t a;
    asm("{ .reg .u64 t; cvta.to.shared.u64 t, %1; cvt.u32.u64 %0, t; }" : "=r"(a) : "l"(p));
    return a;
}
__device__ __forceinline__ void splitHL(float x, u16& h, u16& l) {
    __nv_bfloat16 bh = __float2bfloat16(x);
    __nv_bfloat16 bl = __float2bfloat16(x - __bfloat162float(bh));
    h = __bfloat16_as_ushort(bh);
    l = __bfloat16_as_ushort(bl);
}
__device__ __forceinline__ float joinHL(u16 h, u16 l) {
    return __bfloat162float(__ushort_as_bfloat16(h)) + __bfloat162float(__ushort_as_bfloat16(l));
}
__device__ __forceinline__ void ldsm4(uint32_t* r, uint32_t addr) {
    asm volatile("ldmatrix.sync.aligned.m8n8.x4.shared.b16 {%0,%1,%2,%3}, [%4];"
        : "=r"(r[0]), "=r"(r[1]), "=r"(r[2]), "=r"(r[3]) : "r"(addr));
}
__device__ __forceinline__ void mma16816(float* c, const uint32_t* a, const uint32_t* b) {
    asm volatile("mma.sync.aligned.m16n8k16.row.col.f32.bf16.bf16.f32 "
        "{%0,%1,%2,%3}, {%4,%5,%6,%7}, {%8,%9}, {%0,%1,%2,%3};"
        : "+f"(c[0]), "+f"(c[1]), "+f"(c[2]), "+f"(c[3])
        : "r"(a[0]), "r"(a[1]), "r"(a[2]), "r"(a[3]), "r"(b[0]), "r"(b[1]));
}
__device__ __forceinline__ void cp16(uint32_t dst, const void* src) {
    asm volatile("cp.async.cg.shared.global [%0], [%1], 16;" :: "r"(dst), "l"(src));
}
#define CP_COMMIT() asm volatile("cp.async.commit_group;" ::: "memory")
#define CP_WAIT0()  asm volatile("cp.async.wait_group 0;" ::: "memory")

// ---------------- fused weight conversion ----------------
__global__ void __launch_bounds__(256) convAll(
    const float* __restrict__ Wq, const float* __restrict__ Wk, const float* __restrict__ Wv,
    const float* __restrict__ Wo, const float* __restrict__ W1, const float* __restrict__ Wvq,
    const float* __restrict__ W2)
{
    const int job = blockIdx.z;
    const int r = blockIdx.y;
    const int k0 = blockIdx.x * 256 + threadIdx.x;
    const float* src; u16 *dh, *dl;
    int Kc = 768, rows = 768, inRows = 768;
    switch (job) {
        case 0: src = Wq;  dh = g_wq_hi;                      dl = g_wq_lo;                      break;
        case 1: src = Wk;  dh = g_wq_hi + (size_t)768 * 768;  dl = g_wq_lo + (size_t)768 * 768;  break;
        case 2: src = Wv;  dh = g_wq_hi + (size_t)1536 * 768; dl = g_wq_lo + (size_t)1536 * 768; break;
        case 3: src = Wo;  dh = g_wo_hi; dl = g_wo_lo; break;
        case 4: src = W1;  dh = g_w1_hi; dl = g_w1_lo; rows = 896; inRows = H1C; break;
        case 5: src = Wvq; dh = g_wv_hi; dl = g_wv_lo; break;
        default: src = W2; dh = g_w2_hi; dl = g_w2_lo; Kc = 3072; break;
    }
    if (r >= rows || k0 >= 768) return;
#pragma unroll 4
    for (int j = 0; j < 4; ++j) {
        const int k = k0 + j * 768;
        if (k >= Kc) break;
        float v = (r < inRows) ? src[(size_t)r * Kc + k] : 0.f;
        u16 h, l; splitHL(v, h, l);
        dh[(size_t)r * Kc + k] = h;
        dl[(size_t)r * Kc + k] = l;
    }
}

__global__ void bcat_kernel(const float* __restrict__ a, const float* __restrict__ b,
                            const float* __restrict__ c, float* __restrict__ o) {
    int t = blockIdx.x * 256 + threadIdx.x;
    if (t < 768) o[t] = a[t];
    else if (t < 1536) o[t] = b[t - 768];
    else if (t < 2304) o[t] = c[t - 1536];
}

// ---------------- block reductions ----------------
__device__ __forceinline__ float bred_sum(float v, float* sbuf) {
#pragma unroll
    for (int o = 16; o > 0; o >>= 1) v += __shfl_xor_sync(0xffffffffu, v, o);
    int w = threadIdx.x >> 5, l = threadIdx.x & 31;
    __syncthreads();
    if (l == 0) sbuf[w] = v;
    __syncthreads();
    if (threadIdx.x < 32) {
        float t = (l < 8) ? sbuf[l] : 0.f;
#pragma unroll
        for (int o = 4; o > 0; o >>= 1) t += __shfl_xor_sync(0xffffffffu, t, o);
        if (l == 0) sbuf[32] = t;
    }
    __syncthreads();
    return sbuf[32];
}
__device__ __forceinline__ float bred_max(float v, float* sbuf) {
#pragma unroll
    for (int o = 16; o > 0; o >>= 1) v = fmaxf(v, __shfl_xor_sync(0xffffffffu, v, o));
    int w = threadIdx.x >> 5, l = threadIdx.x & 31;
    __syncthreads();
    if (l == 0) sbuf[w] = v;
    __syncthreads();
    if (threadIdx.x < 32) {
        float t = (l < 8) ? sbuf[l] : -1e30f;
#pragma unroll
        for (int o = 4; o > 0; o >>= 1) t = fmaxf(t, __shfl_xor_sync(0xffffffffu, t, o));
        if (l == 0) sbuf[32] = t;
    }
    __syncthreads();
    return sbuf[32];
}

// ---------------- layernorm -> hi/lo planes ----------------
__global__ void __launch_bounds__(256) ln_split(const float* __restrict__ x,
                                                const float* __restrict__ w,
                                                const float* __restrict__ b,
                                                u16* __restrict__ oh, u16* __restrict__ ol) {
    __shared__ float sbuf[34];
    const int row = blockIdx.x;
    const float* xr = x + (size_t)row * ECFG;
    float v[3];
    float s = 0.f, sq = 0.f;
#pragma unroll
    for (int u = 0; u < 3; ++u) {
        v[u] = xr[threadIdx.x + u * 256];
        s += v[u];
        sq += v[u] * v[u];
    }
    s  = bred_sum(s, sbuf);
    sq = bred_sum(sq, sbuf);
    const float mean = s * (1.0f / ECFG);
    const float inv  = rsqrtf(sq * (1.0f / ECFG) - mean * mean + 1e-5f);
#pragma unroll
    for (int u = 0; u < 3; ++u) {
        int e = threadIdx.x + u * 256;
        u16 h, l; splitHL((v[u] - mean) * inv * w[e] + b[e], h, l);
        oh[(size_t)row * ECFG + e] = h;
        ol[(size_t)row * ECFG + e] = l;
    }
}

// ================= HMMA GEMM, 3-term split, 2-stage cp.async, TM templated ====
// seg0: Ah.Bh  seg1: Al.Bh  seg2: Ah.Bl
// mode 0: C0 = acc + bias (+resid), fp32
// mode 1: QKV -> q planes Q0, k planes Q1 [bh][s][d]; v transposed planes Q2 [bh][d][s]
// mode 2: vqc: A = slice qi of h1s; +bias, GELU -> z planes [gr*3072+gc*4+qi]
// mode 3: fc1: +bias -> 4 shifted h1 slices, gc < colLimit
// mode 4: logits: A,B offset z*65536, C0 offset z<<20, raw fp32
template <int TM>
__global__ void __launch_bounds__(256, 2) hm3(
    const u16* __restrict__ Ahi, const u16* __restrict__ Alo, int ldA,
    const u16* __restrict__ Bhi, const u16* __restrict__ Blo, int ldB,
    const float* __restrict__ bias, const float* __restrict__ resid,
    float* __restrict__ C0, int ldc,
    u16* __restrict__ Q0h, u16* __restrict__ Q0l,
    u16* __restrict__ Q1h, u16* __restrict__ Q1l,
    u16* __restrict__ Q2h, u16* __restrict__ Q2l,
    int Kc, int mode, int colLimit)
{
    constexpr int AF = (TM == 128) ? 4 : 2;     // 16-row a-frags per warp
    constexpr int A_STAGE = TM * 144;           // bytes
    constexpr int B_STAGE = 128 * 144;
    constexpr int STAGE = A_STAGE + B_STAGE;
    extern __shared__ __align__(16) u16 sm[];
    const int t = threadIdx.x, lane = t & 31, wid = t >> 5;
    const int rowBase = blockIdx.y * TM, colBase = blockIdx.x * 128, qi = blockIdx.z;
    if (mode == 2) { Ahi += (size_t)qi * SLICESZ; Alo += (size_t)qi * SLICESZ; }
    if (mode == 4) {
        Ahi += (size_t)qi << 16; Alo += (size_t)qi << 16;
        Bhi += (size_t)qi << 16; Blo += (size_t)qi << 16;
        C0  += (size_t)qi << 20;
    }
    const int mBase = (wid >> 2) * (AF * 16), nBase = (wid & 3) * 32;
    float acc[AF][4][4] = {};

    // A staging mapping
    int srowA, colWA, nCpA;
    if (TM == 128) { srowA = t >> 1; colWA = (t & 1) * 32; nCpA = 4; }
    else           { srowA = t >> 2; colWA = (t & 3) * 16; nCpA = 2; }
    const int srowB = t >> 1;
    const int colWB = (t & 1) * 32;
    const size_t aRowOff = (size_t)(rowBase + srowA) * ldA + colWA;
    const size_t bRowOff = (size_t)(colBase + srowB) * ldB + colWB;
    const uint32_t smb = smem_u32(sm);
    const uint32_t aBuf[2] = { smb,            smb + STAGE };
    const uint32_t bBuf[2] = { smb + A_STAGE,  smb + STAGE + A_STAGE };
    const uint32_t dstOffA = (uint32_t)(srowA * 144 + colWA * 2);
    const uint32_t dstOffB = (uint32_t)(srowB * 144 + colWB * 2);

    const int mat = lane >> 3, lr8 = lane & 7;
    const int rOff = (mat & 1) * 8 + lr8;
    const int cByte = (mat >> 1) * 16;

    const int nk = Kc >> 6;
    const int NIT = nk * 3;

#define HM_ISSUE(IT, BUF) do { \
    const int seg_ = (IT) / nk; \
    const int kb_ = ((IT) - seg_ * nk) * 64; \
    const u16* ap_ = (seg_ == 1 ? Alo : Ahi) + aRowOff + kb_; \
    const u16* bp_ = (seg_ == 2 ? Blo : Bhi) + bRowOff + kb_; \
    const uint32_t ad_ = aBuf[BUF] + dstOffA; \
    const uint32_t bd_ = bBuf[BUF] + dstOffB; \
    _Pragma("unroll") \
    for (int j_ = 0; j_ < nCpA; ++j_) cp16(ad_ + j_ * 16, ap_ + j_ * 8); \
    _Pragma("unroll") \
    for (int j_ = 0; j_ < 4; ++j_) cp16(bd_ + j_ * 16, bp_ + j_ * 8); \
    CP_COMMIT(); \
} while (0)

#define HM_COMPUTE(BUF) do { \
    _Pragma("unroll") \
    for (int s_ = 0; s_ < 4; ++s_) { \
        uint32_t bf_[4][2]; \
        _Pragma("unroll") \
        for (int bp_ = 0; bp_ < 2; ++bp_) { \
            uint32_t r4_[4]; \
            ldsm4(r4_, bBuf[BUF] + (uint32_t)((nBase + bp_ * 16 + rOff) * 144 + cByte + s_ * 32)); \
            bf_[2 * bp_][0] = r4_[0]; bf_[2 * bp_ + 1][0] = r4_[1]; \
            bf_[2 * bp_][1] = r4_[2]; bf_[2 * bp_ + 1][1] = r4_[3]; } \
        _Pragma("unroll") \
        for (int a_ = 0; a_ < AF; ++a_) { \
            uint32_t af_[4]; \
            ldsm4(af_, aBuf[BUF] + (uint32_t)((mBase + a_ * 16 + rOff) * 144 + cByte + s_ * 32)); \
            _Pragma("unroll") \
            for (int bn_ = 0; bn_ < 4; ++bn_) mma16816(acc[a_][bn_], af_, bf_[bn_]); } } \
} while (0)

    HM_ISSUE(0, 0);
    for (int it = 0; it < NIT; ++it) {
        CP_WAIT0();
        __syncthreads();
        if (it + 1 < NIT) HM_ISSUE(it + 1, (it + 1) & 1);
        HM_COMPUTE(it & 1);
    }

    // ---------------- epilogue ----------------
    const int r = lane >> 2, cp = (lane & 3) * 2;
#pragma unroll
    for (int a = 0; a < AF; ++a) {
#pragma unroll
        for (int bn = 0; bn < 4; ++bn) {
            const float* c = acc[a][bn];
            const int gc = colBase + nBase + bn * 8 + cp;
            const float b0 = bias ? bias[gc] : 0.f;
            const float b1 = bias ? bias[gc + 1] : 0.f;
#pragma unroll
            for (int hh = 0; hh < 2; ++hh) {
                const int gr = rowBase + mBase + a * 16 + r + hh * 8;
                float v0 = c[hh * 2] + b0, v1 = c[hh * 2 + 1] + b1;
                if (mode == 0) {
                    if (resid) {
                        v0 += resid[(size_t)gr * ldc + gc];
                        v1 += resid[(size_t)gr * ldc + gc + 1];
                    }
                    *reinterpret_cast<float2*>(C0 + (size_t)gr * ldc + gc) = make_float2(v0, v1);
                } else if (mode == 4) {
                    *reinterpret_cast<float2*>(C0 + (size_t)gr * ldc + gc) = make_float2(v0, v1);
                } else if (mode == 1) {
                    const int which = (gc >= 1536) ? 2 : (gc >= 768 ? 1 : 0);
                    const int e = gc - which * 768;
                    const int h = e >> 6, d = e & 63;
                    const int bb = gr >> 10, s = gr & 1023;
                    u16 h0, l0, h1, l1;
                    splitHL(v0, h0, l0); splitHL(v1, h1, l1);
                    if (which < 2) {
                        u16* dh = which == 0 ? Q0h : Q1h;
                        u16* dl = which == 0 ? Q0l : Q1l;
                        const size_t base = (((size_t)(bb * HCFG + h)) * SCFG + s) * DCFG + d;
                        dh[base] = h0; dh[base + 1] = h1;
                        dl[base] = l0; dl[base + 1] = l1;
                    } else {
                        const size_t base = ((size_t)(bb * HCFG + h)) * DCFG * SCFG + (size_t)d * SCFG + s;
                        Q2h[base] = h0; Q2h[base + SCFG] = h1;
                        Q2l[base] = l0; Q2l[base + SCFG] = l1;
                    }
                } else if (mode == 2) {
                    const float g0 = 0.5f * v0 * (1.0f + erff(v0 * 0.70710678118654752f));
                    const float g1 = 0.5f * v1 * (1.0f + erff(v1 * 0.70710678118654752f));
                    u16 h0, l0, h1, l1;
                    splitHL(g0, h0, l0); splitHL(g1, h1, l1);
                    const size_t base = (size_t)gr * QMCFG + (size_t)gc * 4 + qi;
                    Q0h[base] = h0; Q0h[base + 4] = h1;
                    Q0l[base] = l0; Q0l[base + 4] = l1;
                } else {
                    u16 h0, l0, h1, l1;
                    splitHL(v0, h0, l0); splitHL(v1, h1, l1);
#pragma unroll
                    for (int qq = 0; qq < 4; ++qq) {
                        const int c0 = gc - qq, c1 = gc + 1 - qq;
                        const size_t sb = (size_t)qq * SLICESZ + (size_t)gr * 768;
                        if (c0 >= 0 && c0 < 768 && gc < colLimit)     { Q0h[sb + c0] = h0; Q0l[sb + c0] = l0; }
                        if (c1 >= 0 && c1 < 768 && gc + 1 < colLimit) { Q0h[sb + c1] = h1; Q0l[sb + c1] = l1; }
                    }
                }
            }
        }
    }
}
#define HM_SMEM_128 (2 * (128 * 144 + 128 * 144))
#define HM_SMEM_64  (2 * (64 * 144 + 128 * 144))

// ================= PV HMMA, 3-term split, 2-stage pipeline =================
#define PV_STAGE_A 18432
#define PV_STAGE_B 9216
#define PV_SMEM (2 * (PV_STAGE_A + PV_STAGE_B))
__global__ void __launch_bounds__(256, 2) pv3(
    const u16* __restrict__ Phi, const u16* __restrict__ Plo,
    const u16* __restrict__ Vhi, const u16* __restrict__ Vlo,
    u16* __restrict__ vh, u16* __restrict__ vl)
{
    extern __shared__ __align__(16) u16 sm[];
    const int t = threadIdx.x, lane = t & 31, wid = t >> 5;
    const int bh = blockIdx.y;
    const int rowBase = blockIdx.x * 128;
    const u16* Ahi = Phi + ((size_t)bh << 20);
    const u16* Alo = Plo + ((size_t)bh << 20);
    const u16* Bhi = Vhi + (size_t)bh * DCFG * SCFG;
    const u16* Blo = Vlo + (size_t)bh * DCFG * SCFG;
    const int mBase = (wid >> 1) * 32, nBase = (wid & 1) * 32;
    float acc[2][4][4] = {};

    const int srow = t >> 1, half = t & 1;
    const size_t aRowOff = (size_t)(rowBase + srow) * SCFG + half * 32;
    const int srowB = (t & 127) >> 1;
    const size_t bRowOff = (size_t)srowB * SCFG + half * 32;
    const bool doB = t < 128;

    const uint32_t smb = smem_u32(sm);
    const uint32_t aBuf[2] = { smb, smb + PV_STAGE_A + PV_STAGE_B };
    const uint32_t bBuf[2] = { aBuf[0] + PV_STAGE_A, aBuf[1] + PV_STAGE_A };
    const uint32_t dstOffA = (uint32_t)(srow * 72 + half * 32) * 2;
    const uint32_t dstOffB = (uint32_t)(srowB * 72 + half * 32) * 2;

    const int mat = lane >> 3, lr8 = lane & 7;
    const int rOff = (mat & 1) * 8 + lr8;
    const int cByte = (mat >> 1) * 16;

    const int nk = SCFG >> 6;
    const int NIT = nk * 3;

#define PV_ISSUE(IT, BUF) do { \
    const int seg_ = (IT) / nk; \
    const int kb_ = ((IT) - seg_ * nk) * 64; \
    const u16* ap_ = (seg_ == 1 ? Alo : Ahi) + aRowOff + kb_; \
    const uint32_t ad_ = aBuf[BUF] + dstOffA; \
    _Pragma("unroll") \
    for (int j_ = 0; j_ < 4; ++j_) cp16(ad_ + j_ * 16, ap_ + j_ * 8); \
    if (doB) { \
        const u16* bp_ = (seg_ == 2 ? Blo : Bhi) + bRowOff + kb_; \
        const uint32_t bd_ = bBuf[BUF] + dstOffB; \
        _Pragma("unroll") \
        for (int j_ = 0; j_ < 4; ++j_) cp16(bd_ + j_ * 16, bp_ + j_ * 8); } \
    CP_COMMIT(); \
} while (0)

#define PV_COMPUTE(BUF) do { \
    _Pragma("unroll") \
    for (int s_ = 0; s_ < 4; ++s_) { \
        uint32_t bf_[4][2]; \
        _Pragma("unroll") \
        for (int bp_ = 0; bp_ < 2; ++bp_) { \
            uint32_t r4_[4]; \
            ldsm4(r4_, bBuf[BUF] + (uint32_t)((nBase + bp_ * 16 + rOff) * 144 + cByte + s_ * 32)); \
            bf_[2 * bp_][0] = r4_[0]; bf_[2 * bp_ + 1][0] = r4_[1]; \
            bf_[2 * bp_][1] = r4_[2]; bf_[2 * bp_ + 1][1] = r4_[3]; } \
        _Pragma("unroll") \
        for (int a_ = 0; a_ < 2; ++a_) { \
            uint32_t af_[4]; \
            ldsm4(af_, aBuf[BUF] + (uint32_t)((mBase + a_ * 16 + rOff) * 144 + cByte + s_ * 32)); \
            _Pragma("unroll") \
            for (int bn_ = 0; bn_ < 4; ++bn_) mma16816(acc[a_][bn_], af_, bf_[bn_]); } } \
} while (0)

    PV_ISSUE(0, 0);
    for (int it = 0; it < NIT; ++it) {
        CP_WAIT0();
        __syncthreads();
        if (it + 1 < NIT) PV_ISSUE(it + 1, (it + 1) & 1);
        PV_COMPUTE(it & 1);
    }

    const int b = bh / HCFG, h = bh % HCFG;
    const int r = lane >> 2, cp = (lane & 3) * 2;
#pragma unroll
    for (int a = 0; a < 2; ++a) {
#pragma unroll
        for (int bn = 0; bn < 4; ++bn) {
            const float* c = acc[a][bn];
            const int d = nBase + bn * 8 + cp;
#pragma unroll
            for (int hh = 0; hh < 2; ++hh) {
                const int s = rowBase + mBase + a * 16 + r + hh * 8;
                const size_t base = ((size_t)(b * SCFG + s)) * ECFG + h * DCFG + d;
                u16 h0, l0, h1, l1;
                splitHL(c[hh * 2], h0, l0); splitHL(c[hh * 2 + 1], h1, l1);
                vh[base] = h0; vh[base + 1] = h1;
                vl[base] = l0; vl[base + 1] = l1;
            }
        }
    }
}

// ---------------- row norms from planes ----------------
__global__ void norm_planes(const u16* __restrict__ sh, const u16* __restrict__ sl,
                            float* __restrict__ dst, int nrows) {
    const int r = blockIdx.x * blockDim.x + threadIdx.x;
    if (r >= nrows) return;
    const uint4* ph = reinterpret_cast<const uint4*>(sh + (size_t)r * DCFG);
    const uint4* pl = reinterpret_cast<const uint4*>(sl + (size_t)r * DCFG);
    float s = 0.f;
#pragma unroll
    for (int i = 0; i < 8; ++i) {
        uint4 th = ph[i], tl = pl[i];
        const uint32_t* wh = &th.x;
        const uint32_t* wl = &tl.x;
#pragma unroll
        for (int j = 0; j < 4; ++j) {
            float a = joinHL((u16)(wh[j] & 0xffffu), (u16)(wl[j] & 0xffffu));
            float b = joinHL((u16)(wh[j] >> 16),     (u16)(wl[j] >> 16));
            s += a * a + b * b;
        }
    }
    dst[r] = s;
}

// ---------------- softmax + RBF mix ----------------
__global__ void __launch_bounds__(256) mix_kernel(const float* __restrict__ P,
                                                  u16* __restrict__ Ph, u16* __restrict__ Pl,
                                                  const float* __restrict__ qn_,
                                                  const float* __restrict__ kn_,
                                                  const float* __restrict__ pond) {
    __shared__ float sbuf[34];
    const int row = blockIdx.x;
    const int bh  = row >> 10;
    const float* prow = P + (size_t)row * SCFG;
    const float* knb = kn_ + (size_t)bh * SCFG;
    const int tid = threadIdx.x;
    const float qn = qn_[row];
    const float sigma2 = fminf(fmaxf(qn, 1e-8f), 1e4f);

    float4 dt  = *reinterpret_cast<const float4*>(prow + tid * 4);
    float4 kn4 = *reinterpret_cast<const float4*>(knb + tid * 4);
    const float d[4]  = {dt.x, dt.y, dt.z, dt.w};
    const float kn[4] = {kn4.x, kn4.y, kn4.z, kn4.w};

    float lm = -1e30f;
#pragma unroll
    for (int u = 0; u < 4; ++u) lm = fmaxf(lm, d[u] * 0.125f);
    const float M = bred_max(lm, sbuf);

    float e[4], rb[4];
    float se = 0.f, sr = 0.f;
#pragma unroll
    for (int u = 0; u < 4; ++u) {
        e[u] = expf(d[u] * 0.125f - M);
        se += e[u];
        const float d2 = fmaxf(qn + kn[u] - 2.f * d[u], 0.f);
        rb[u] = expf(-d2 / sigma2);
        sr += rb[u];
    }
    const float Ls = bred_sum(se, sbuf);
    const float Lr = bred_sum(sr, sbuf);

    const float sv = 1.f / (1.f + expf(-pond[0]));
    const float p0 = 1.f - sv, p1 = sv;
    const float inv = 1.f / (p0 + p1 + 1e-7f);
    const float ca = p0 * inv / Ls;
    const float cb = p1 * inv / fmaxf(Lr, 1e-8f);

    u16 h[4], l[4];
#pragma unroll
    for (int u = 0; u < 4; ++u) splitHL(ca * e[u] + cb * rb[u], h[u], l[u]);
    uint2 ho, lo;
    ho.x = (uint32_t)h[0] | ((uint32_t)h[1] << 16);
    ho.y = (uint32_t)h[2] | ((uint32_t)h[3] << 16);
    lo.x = (uint32_t)l[0] | ((uint32_t)l[1] << 16);
    lo.y = (uint32_t)l[2] | ((uint32_t)l[3] << 16);
    *reinterpret_cast<uint2*>(Ph + (size_t)row * SCFG + tid * 4) = ho;
    *reinterpret_cast<uint2*>(Pl + (size_t)row * SCFG + tid * 4) = lo;
}

// ---------------- launch ----------------
extern "C" void kernel_launch(void* const* d_in, const int* in_sizes, int n_in,
                              void* d_out, int out_size) {
    const float* x     = (const float*)d_in[0];
    const float* ln1_w = (const float*)d_in[1];
    const float* ln1_b = (const float*)d_in[2];
    const float* Wq    = (const float*)d_in[3];
    const float* bq    = (const float*)d_in[4];
    const float* Wk    = (const float*)d_in[5];
    const float* bk    = (const float*)d_in[6];
    const float* Wv    = (const float*)d_in[7];
    const float* bv    = (const float*)d_in[8];
    const float* Wo    = (const float*)d_in[9];
    const float* bo    = (const float*)d_in[10];
    const float* pond  = (const float*)d_in[11];
    const float* ln2_w = (const float*)d_in[12];
    const float* ln2_b = (const float*)d_in[13];
    const float* fc1_W = (const float*)d_in[14];
    const float* fc1_b = (const float*)d_in[15];
    const float* vqc_W = (const float*)d_in[16];
    const float* vqc_b = (const float*)d_in[17];
    const float* fc2_W = (const float*)d_in[18];
    const float* fc2_b = (const float*)d_in[19];
    float* out = (float*)d_out;

    cudaFuncSetAttribute(hm3<128>, cudaFuncAttributeMaxDynamicSharedMemorySize, HM_SMEM_128);
    cudaFuncSetAttribute(hm3<64>,  cudaFuncAttributeMaxDynamicSharedMemorySize, HM_SMEM_64);
    cudaFuncSetAttribute(pv3, cudaFuncAttributeMaxDynamicSharedMemorySize, PV_SMEM);

    float *p_bqkv, *p_qn, *p_kn, *p_P, *p_x1;
    u16 *p_h_hi, *p_h_lo, *p_wq_hi, *p_wq_lo, *p_q_hi, *p_q_lo, *p_k_hi, *p_k_lo;
    u16 *p_vt_hi, *p_vt_lo, *p_P_hi, *p_P_lo, *p_va_hi, *p_va_lo, *p_wo_hi, *p_wo_lo;
    u16 *p_y_hi, *p_y_lo, *p_w1_hi, *p_w1_lo, *p_h1s_hi, *p_h1s_lo, *p_wv_hi, *p_wv_lo;
    u16 *p_z_hi, *p_z_lo, *p_w2_hi, *p_w2_lo;
    cudaGetSymbolAddress((void**)&p_bqkv, g_bqkv);
    cudaGetSymbolAddress((void**)&p_qn, g_qn);
    cudaGetSymbolAddress((void**)&p_kn, g_kn);
    cudaGetSymbolAddress((void**)&p_P, g_P);
    cudaGetSymbolAddress((void**)&p_x1, g_x1);
    cudaGetSymbolAddress((void**)&p_h_hi, g_h_hi);     cudaGetSymbolAddress((void**)&p_h_lo, g_h_lo);
    cudaGetSymbolAddress((void**)&p_wq_hi, g_wq_hi);   cudaGetSymbolAddress((void**)&p_wq_lo, g_wq_lo);
    cudaGetSymbolAddress((void**)&p_q_hi, g_q_hi);     cudaGetSymbolAddress((void**)&p_q_lo, g_q_lo);
    cudaGetSymbolAddress((void**)&p_k_hi, g_k_hi);     cudaGetSymbolAddress((void**)&p_k_lo, g_k_lo);
    cudaGetSymbolAddress((void**)&p_vt_hi, g_vt_hi);   cudaGetSymbolAddress((void**)&p_vt_lo, g_vt_lo);
    cudaGetSymbolAddress((void**)&p_P_hi, g_P_hi);     cudaGetSymbolAddress((void**)&p_P_lo, g_P_lo);
    cudaGetSymbolAddress((void**)&p_va_hi, g_va_hi);   cudaGetSymbolAddress((void**)&p_va_lo, g_va_lo);
    cudaGetSymbolAddress((void**)&p_wo_hi, g_wo_hi);   cudaGetSymbolAddress((void**)&p_wo_lo, g_wo_lo);
    cudaGetSymbolAddress((void**)&p_y_hi, g_y_hi);     cudaGetSymbolAddress((void**)&p_y_lo, g_y_lo);
    cudaGetSymbolAddress((void**)&p_w1_hi, g_w1_hi);   cudaGetSymbolAddress((void**)&p_w1_lo, g_w1_lo);
    cudaGetSymbolAddress((void**)&p_h1s_hi, g_h1s_hi); cudaGetSymbolAddress((void**)&p_h1s_lo, g_h1s_lo);
    cudaGetSymbolAddress((void**)&p_wv_hi, g_wv_hi);   cudaGetSymbolAddress((void**)&p_wv_lo, g_wv_lo);
    cudaGetSymbolAddress((void**)&p_z_hi, g_z_hi);     cudaGetSymbolAddress((void**)&p_z_lo, g_z_lo);
    cudaGetSymbolAddress((void**)&p_w2_hi, g_w2_hi);   cudaGetSymbolAddress((void**)&p_w2_lo, g_w2_lo);

    // 0) fused weight conversions + bias concat
    convAll<<<dim3(3, 896, 7), 256>>>(Wq, Wk, Wv, Wo, fc1_W, vqc_W, fc2_W);
    bcat_kernel<<<9, 256>>>(bq, bk, bv, p_bqkv);

    // 1) LN1 -> h planes
    ln_split<<<NTOK, 256>>>(x, ln1_w, ln1_b, p_h_hi, p_h_lo);

    // 2) fused QKV (TM=128, grid 288)
    hm3<128><<<dim3(18, 16), 256, HM_SMEM_128>>>(p_h_hi, p_h_lo, ECFG, p_wq_hi, p_wq_lo, ECFG,
                                                 p_bqkv, nullptr, nullptr, 0,
                                                 p_q_hi, p_q_lo, p_k_hi, p_k_lo, p_vt_hi, p_vt_lo,
                                                 768, 1, 0);

    // 3) norms
    norm_planes<<<(BHCFG * SCFG + 255) / 256, 256>>>(p_q_hi, p_q_lo, p_qn, BHCFG * SCFG);
    norm_planes<<<(BHCFG * SCFG + 255) / 256, 256>>>(p_k_hi, p_k_lo, p_kn, BHCFG * SCFG);

    // 4) logits (TM=128, grid 1536)
    hm3<128><<<dim3(8, 8, BHCFG), 256, HM_SMEM_128>>>(p_q_hi, p_q_lo, DCFG, p_k_hi, p_k_lo, DCFG,
                                                      nullptr, nullptr, p_P, SCFG,
                                                      nullptr, nullptr, nullptr, nullptr, nullptr, nullptr,
                                                      64, 4, 0);

    // 5) softmax + RBF -> P planes
    mix_kernel<<<BHCFG * SCFG, 256>>>(p_P, p_P_hi, p_P_lo, p_qn, p_kn, pond);

    // 6) P @ V -> vals planes (grid 192)
    pv3<<<dim3(8, BHCFG), 256, PV_SMEM>>>(p_P_hi, p_P_lo, p_vt_hi, p_vt_lo, p_va_hi, p_va_lo);

    // 7) x1 = x + vals@Wo^T + bo (TM=64, grid 192)
    hm3<64><<<dim3(6, 32), 256, HM_SMEM_64>>>(p_va_hi, p_va_lo, ECFG, p_wo_hi, p_wo_lo, ECFG,
                                              bo, x, p_x1, ECFG,
                                              nullptr, nullptr, nullptr, nullptr, nullptr, nullptr,
                                              768, 0, 0);

    // 8) LN2 -> y planes
    ln_split<<<NTOK, 256>>>(p_x1, ln2_w, ln2_b, p_y_hi, p_y_lo);

    // 9) fc1 -> 4 pre-shifted h1 slices (TM=64, grid 224)
    hm3<64><<<dim3(7, 32), 256, HM_SMEM_64>>>(p_y_hi, p_y_lo, ECFG, p_w1_hi, p_w1_lo, ECFG,
                                              fc1_b, nullptr, nullptr, 0,
                                              p_h1s_hi, p_h1s_lo, nullptr, nullptr, nullptr, nullptr,
                                              768, 3, H1C);

    // 10) vqc + GELU -> z planes (TM=128, grid 384)
    hm3<128><<<dim3(6, 16, 4), 256, HM_SMEM_128>>>(p_h1s_hi, p_h1s_lo, 768, p_wv_hi, p_wv_lo, ECFG,
                                                   vqc_b, nullptr, nullptr, 0,
                                                   p_z_hi, p_z_lo, nullptr, nullptr, nullptr, nullptr,
                                                   768, 2, 0);

    // 11) out = x1 + z@fc2^T + fc2_b (TM=64, grid 192)
    hm3<64><<<dim3(6, 32), 256, HM_SMEM_64>>>(p_z_hi, p_z_lo, QMCFG, p_w2_hi, p_w2_lo, QMCFG,
                                              fc2_b, p_x1, out, ECFG,
                                              nullptr, nullptr, nullptr, nullptr, nullptr, nullptr,
                                              3072, 0, 0);

    (void)in_sizes; (void)n_in; (void)out_size;
}

// round 11
// speedup vs baseline: 1.3492x; 1.2951x over previous
#include <cuda_runtime.h>
#include <cuda_fp16.h>
#include <cstdint>
#include <math.h>

#define NTOK   2048
#define ECFG   768
#define SCFG   1024
#define HCFG   12
#define DCFG   64
#define BHCFG  24
#define QMCFG  3072
#define H1C    771
#define SLICESZ ((size_t)NTOK * 768)

typedef unsigned short u16;

// ---------------- scratch: hi/lo fp16 planes ----------------
__device__ __align__(16) u16 g_h_hi [NTOK * ECFG];
__device__ __align__(16) u16 g_h_lo [NTOK * ECFG];
__device__ __align__(16) u16 g_wq_hi[(size_t)2304 * ECFG];
__device__ __align__(16) u16 g_wq_lo[(size_t)2304 * ECFG];
__device__ float g_bqkv[2304];
__device__ __align__(16) u16 g_q_hi [BHCFG * SCFG * DCFG];
__device__ __align__(16) u16 g_q_lo [BHCFG * SCFG * DCFG];
__device__ __align__(16) u16 g_k_hi [BHCFG * SCFG * DCFG];
__device__ __align__(16) u16 g_k_lo [BHCFG * SCFG * DCFG];
__device__ __align__(16) u16 g_vt_hi[BHCFG * DCFG * SCFG];
__device__ __align__(16) u16 g_vt_lo[BHCFG * DCFG * SCFG];
__device__ float g_qn[BHCFG * SCFG];
__device__ float g_kn[BHCFG * SCFG];
__device__ float g_P [(size_t)BHCFG * SCFG * SCFG];
__device__ __align__(16) u16 g_P_hi[(size_t)BHCFG * SCFG * SCFG];
__device__ __align__(16) u16 g_P_lo[(size_t)BHCFG * SCFG * SCFG];
__device__ __align__(16) u16 g_va_hi[NTOK * ECFG];
__device__ __align__(16) u16 g_va_lo[NTOK * ECFG];
__device__ __align__(16) u16 g_wo_hi[(size_t)ECFG * ECFG];
__device__ __align__(16) u16 g_wo_lo[(size_t)ECFG * ECFG];
__device__ float g_x1[NTOK * ECFG];
__device__ __align__(16) u16 g_y_hi [NTOK * ECFG];
__device__ __align__(16) u16 g_y_lo [NTOK * ECFG];
__device__ __align__(16) u16 g_w1_hi[(size_t)896 * ECFG];
__device__ __align__(16) u16 g_w1_lo[(size_t)896 * ECFG];
__device__ __align__(16) u16 g_h1s_hi[4 * SLICESZ];
__device__ __align__(16) u16 g_h1s_lo[4 * SLICESZ];
__device__ __align__(16) u16 g_wv_hi[(size_t)ECFG * ECFG];
__device__ __align__(16) u16 g_wv_lo[(size_t)ECFG * ECFG];
__device__ __align__(16) u16 g_z_hi [(size_t)NTOK * QMCFG];
__device__ __align__(16) u16 g_z_lo [(size_t)NTOK * QMCFG];
__device__ __align__(16) u16 g_w2_hi[(size_t)ECFG * QMCFG];
__device__ __align__(16) u16 g_w2_lo[(size_t)ECFG * QMCFG];

// ---------------- helpers ----------------
__device__ __forceinline__ uint32_t smem_u32(const void* p) {
    uint32_t a;
    asm("{ .reg .u64 t; cvta.to.shared.u64 t, %1; cvt.u32.u64 %0, t; }" : "=r"(a) : "l"(p));
    return a;
}
__device__ __forceinline__ void splitHL(float x, u16& h, u16& l) {
    __half hh = __float2half_rn(x);
    __half ll = __float2half_rn(x - __half2float(hh));
    h = __half_as_ushort(hh);
    l = __half_as_ushort(ll);
}
__device__ __forceinline__ float joinHL(u16 h, u16 l) {
    return __half2float(__ushort_as_half(h)) + __half2float(__ushort_as_half(l));
}
__device__ __forceinline__ void ldsm4(uint32_t* r, uint32_t addr) {
    asm volatile("ldmatrix.sync.aligned.m8n8.x4.shared.b16 {%0,%1,%2,%3}, [%4];"
        : "=r"(r[0]), "=r"(r[1]), "=r"(r[2]), "=r"(r[3]) : "r"(addr));
}
__device__ __forceinline__ void mma16816(float* c, const uint32_t* a, const uint32_t* b) {
    asm volatile("mma.sync.aligned.m16n8k16.row.col.f32.f16.f16.f32 "
        "{%0,%1,%2,%3}, {%4,%5,%6,%7}, {%8,%9}, {%0,%1,%2,%3};"
        : "+f"(c[0]), "+f"(c[1]), "+f"(c[2]), "+f"(c[3])
        : "r"(a[0]), "r"(a[1]), "r"(a[2]), "r"(a[3]), "r"(b[0]), "r"(b[1]));
}
__device__ __forceinline__ void cp16(uint32_t dst, const void* src) {
    asm volatile("cp.async.cg.shared.global [%0], [%1], 16;" :: "r"(dst), "l"(src));
}
#define CP_COMMIT() asm volatile("cp.async.commit_group;" ::: "memory")
#define CP_WAIT0()  asm volatile("cp.async.wait_group 0;" ::: "memory")

// ---------------- fused weight conversion ----------------
__global__ void __launch_bounds__(256) convAll(
    const float* __restrict__ Wq, const float* __restrict__ Wk, const float* __restrict__ Wv,
    const float* __restrict__ Wo, const float* __restrict__ W1, const float* __restrict__ Wvq,
    const float* __restrict__ W2)
{
    const int job = blockIdx.z;
    const int r = blockIdx.y;
    const int k0 = blockIdx.x * 256 + threadIdx.x;
    const float* src; u16 *dh, *dl;
    int Kc = 768, rows = 768, inRows = 768;
    switch (job) {
        case 0: src = Wq;  dh = g_wq_hi;                      dl = g_wq_lo;                      break;
        case 1: src = Wk;  dh = g_wq_hi + (size_t)768 * 768;  dl = g_wq_lo + (size_t)768 * 768;  break;
        case 2: src = Wv;  dh = g_wq_hi + (size_t)1536 * 768; dl = g_wq_lo + (size_t)1536 * 768; break;
        case 3: src = Wo;  dh = g_wo_hi; dl = g_wo_lo; break;
        case 4: src = W1;  dh = g_w1_hi; dl = g_w1_lo; rows = 896; inRows = H1C; break;
        case 5: src = Wvq; dh = g_wv_hi; dl = g_wv_lo; break;
        default: src = W2; dh = g_w2_hi; dl = g_w2_lo; Kc = 3072; break;
    }
    if (r >= rows || k0 >= 768) return;
#pragma unroll 4
    for (int j = 0; j < 4; ++j) {
        const int k = k0 + j * 768;
        if (k >= Kc) break;
        float v = (r < inRows) ? src[(size_t)r * Kc + k] : 0.f;
        u16 h, l; splitHL(v, h, l);
        dh[(size_t)r * Kc + k] = h;
        dl[(size_t)r * Kc + k] = l;
    }
}

__global__ void bcat_kernel(const float* __restrict__ a, const float* __restrict__ b,
                            const float* __restrict__ c, float* __restrict__ o) {
    int t = blockIdx.x * 256 + threadIdx.x;
    if (t < 768) o[t] = a[t];
    else if (t < 1536) o[t] = b[t - 768];
    else if (t < 2304) o[t] = c[t - 1536];
}

// ---------------- block reductions ----------------
__device__ __forceinline__ float bred_sum(float v, float* sbuf) {
#pragma unroll
    for (int o = 16; o > 0; o >>= 1) v += __shfl_xor_sync(0xffffffffu, v, o);
    int w = threadIdx.x >> 5, l = threadIdx.x & 31;
    __syncthreads();
    if (l == 0) sbuf[w] = v;
    __syncthreads();
    if (threadIdx.x < 32) {
        float t = (l < 8) ? sbuf[l] : 0.f;
#pragma unroll
        for (int o = 4; o > 0; o >>= 1) t += __shfl_xor_sync(0xffffffffu, t, o);
        if (l == 0) sbuf[32] = t;
    }
    __syncthreads();
    return sbuf[32];
}
__device__ __forceinline__ float bred_max(float v, float* sbuf) {
#pragma unroll
    for (int o = 16; o > 0; o >>= 1) v = fmaxf(v, __shfl_xor_sync(0xffffffffu, v, o));
    int w = threadIdx.x >> 5, l = threadIdx.x & 31;
    __syncthreads();
    if (l == 0) sbuf[w] = v;
    __syncthreads();
    if (threadIdx.x < 32) {
        float t = (l < 8) ? sbuf[l] : -1e30f;
#pragma unroll
        for (int o = 4; o > 0; o >>= 1) t = fmaxf(t, __shfl_xor_sync(0xffffffffu, t, o));
        if (l == 0) sbuf[32] = t;
    }
    __syncthreads();
    return sbuf[32];
}

// ---------------- layernorm -> hi/lo planes ----------------
__global__ void __launch_bounds__(256) ln_split(const float* __restrict__ x,
                                                const float* __restrict__ w,
                                                const float* __restrict__ b,
                                                u16* __restrict__ oh, u16* __restrict__ ol) {
    __shared__ float sbuf[34];
    const int row = blockIdx.x;
    const float* xr = x + (size_t)row * ECFG;
    float v[3];
    float s = 0.f, sq = 0.f;
#pragma unroll
    for (int u = 0; u < 3; ++u) {
        v[u] = xr[threadIdx.x + u * 256];
        s += v[u];
        sq += v[u] * v[u];
    }
    s  = bred_sum(s, sbuf);
    sq = bred_sum(sq, sbuf);
    const float mean = s * (1.0f / ECFG);
    const float inv  = rsqrtf(sq * (1.0f / ECFG) - mean * mean + 1e-5f);
#pragma unroll
    for (int u = 0; u < 3; ++u) {
        int e = threadIdx.x + u * 256;
        u16 h, l; splitHL((v[u] - mean) * inv * w[e] + b[e], h, l);
        oh[(size_t)row * ECFG + e] = h;
        ol[(size_t)row * ECFG + e] = l;
    }
}

// ================= HMMA GEMM, fp16 split, 2-stage cp.async, TM templated ====
// nseg=2: seg0 Ah.Bh, seg1 Al.Bh      (dense: A exact-split, W single fp16)
// nseg=3: + seg2 Ah.Bl                (logits: both operands split)
// mode 0: C0 = acc + bias (+resid), fp32
// mode 1: QKV -> q planes Q0, k planes Q1 [bh][s][d]; v transposed planes Q2 [bh][d][s]
// mode 2: vqc: A = slice qi of h1s; +bias, GELU -> z planes [gr*3072+gc*4+qi]
// mode 3: fc1: +bias -> 4 shifted h1 slices, gc < colLimit
// mode 4: logits: A,B offset z*65536, C0 offset z<<20, raw fp32
template <int TM>
__global__ void __launch_bounds__(256, 2) hm3(
    const u16* __restrict__ Ahi, const u16* __restrict__ Alo, int ldA,
    const u16* __restrict__ Bhi, const u16* __restrict__ Blo, int ldB,
    const float* __restrict__ bias, const float* __restrict__ resid,
    float* __restrict__ C0, int ldc,
    u16* __restrict__ Q0h, u16* __restrict__ Q0l,
    u16* __restrict__ Q1h, u16* __restrict__ Q1l,
    u16* __restrict__ Q2h, u16* __restrict__ Q2l,
    int Kc, int mode, int colLimit, int nseg)
{
    constexpr int AF = (TM == 128) ? 4 : 2;
    constexpr int A_STAGE = TM * 144;
    constexpr int B_STAGE = 128 * 144;
    constexpr int STAGE = A_STAGE + B_STAGE;
    extern __shared__ __align__(16) u16 sm[];
    const int t = threadIdx.x, lane = t & 31, wid = t >> 5;
    const int rowBase = blockIdx.y * TM, colBase = blockIdx.x * 128, qi = blockIdx.z;
    if (mode == 2) { Ahi += (size_t)qi * SLICESZ; Alo += (size_t)qi * SLICESZ; }
    if (mode == 4) {
        Ahi += (size_t)qi << 16; Alo += (size_t)qi << 16;
        Bhi += (size_t)qi << 16; Blo += (size_t)qi << 16;
        C0  += (size_t)qi << 20;
    }
    const int mBase = (wid >> 2) * (AF * 16), nBase = (wid & 3) * 32;
    float acc[AF][4][4] = {};

    int srowA, colWA, nCpA;
    if (TM == 128) { srowA = t >> 1; colWA = (t & 1) * 32; nCpA = 4; }
    else           { srowA = t >> 2; colWA = (t & 3) * 16; nCpA = 2; }
    const int srowB = t >> 1;
    const int colWB = (t & 1) * 32;
    const size_t aRowOff = (size_t)(rowBase + srowA) * ldA + colWA;
    const size_t bRowOff = (size_t)(colBase + srowB) * ldB + colWB;
    const uint32_t smb = smem_u32(sm);
    const uint32_t aBuf[2] = { smb,            smb + STAGE };
    const uint32_t bBuf[2] = { smb + A_STAGE,  smb + STAGE + A_STAGE };
    const uint32_t dstOffA = (uint32_t)(srowA * 144 + colWA * 2);
    const uint32_t dstOffB = (uint32_t)(srowB * 144 + colWB * 2);

    const int mat = lane >> 3, lr8 = lane & 7;
    const int rOff = (mat & 1) * 8 + lr8;
    const int cByte = (mat >> 1) * 16;

    const int nk = Kc >> 6;
    const int NIT = nk * nseg;

#define HM_ISSUE(IT, BUF) do { \
    const int seg_ = (IT) / nk; \
    const int kb_ = ((IT) - seg_ * nk) * 64; \
    const u16* ap_ = (seg_ == 1 ? Alo : Ahi) + aRowOff + kb_; \
    const u16* bp_ = (seg_ == 2 ? Blo : Bhi) + bRowOff + kb_; \
    const uint32_t ad_ = aBuf[BUF] + dstOffA; \
    const uint32_t bd_ = bBuf[BUF] + dstOffB; \
    _Pragma("unroll") \
    for (int j_ = 0; j_ < nCpA; ++j_) cp16(ad_ + j_ * 16, ap_ + j_ * 8); \
    _Pragma("unroll") \
    for (int j_ = 0; j_ < 4; ++j_) cp16(bd_ + j_ * 16, bp_ + j_ * 8); \
    CP_COMMIT(); \
} while (0)

#define HM_COMPUTE(BUF) do { \
    _Pragma("unroll") \
    for (int s_ = 0; s_ < 4; ++s_) { \
        uint32_t bf_[4][2]; \
        _Pragma("unroll") \
        for (int bp_ = 0; bp_ < 2; ++bp_) { \
            uint32_t r4_[4]; \
            ldsm4(r4_, bBuf[BUF] + (uint32_t)((nBase + bp_ * 16 + rOff) * 144 + cByte + s_ * 32)); \
            bf_[2 * bp_][0] = r4_[0]; bf_[2 * bp_ + 1][0] = r4_[1]; \
            bf_[2 * bp_][1] = r4_[2]; bf_[2 * bp_ + 1][1] = r4_[3]; } \
        _Pragma("unroll") \
        for (int a_ = 0; a_ < AF; ++a_) { \
            uint32_t af_[4]; \
            ldsm4(af_, aBuf[BUF] + (uint32_t)((mBase + a_ * 16 + rOff) * 144 + cByte + s_ * 32)); \
            _Pragma("unroll") \
            for (int bn_ = 0; bn_ < 4; ++bn_) mma16816(acc[a_][bn_], af_, bf_[bn_]); } } \
} while (0)

    HM_ISSUE(0, 0);
    for (int it = 0; it < NIT; ++it) {
        CP_WAIT0();
        __syncthreads();
        if (it + 1 < NIT) HM_ISSUE(it + 1, (it + 1) & 1);
        HM_COMPUTE(it & 1);
    }

    // ---------------- epilogue ----------------
    const int r = lane >> 2, cp = (lane & 3) * 2;
#pragma unroll
    for (int a = 0; a < AF; ++a) {
#pragma unroll
        for (int bn = 0; bn < 4; ++bn) {
            const float* c = acc[a][bn];
            const int gc = colBase + nBase + bn * 8 + cp;
            const float b0 = bias ? bias[gc] : 0.f;
            const float b1 = bias ? bias[gc + 1] : 0.f;
#pragma unroll
            for (int hh = 0; hh < 2; ++hh) {
                const int gr = rowBase + mBase + a * 16 + r + hh * 8;
                float v0 = c[hh * 2] + b0, v1 = c[hh * 2 + 1] + b1;
                if (mode == 0) {
                    if (resid) {
                        v0 += resid[(size_t)gr * ldc + gc];
                        v1 += resid[(size_t)gr * ldc + gc + 1];
                    }
                    *reinterpret_cast<float2*>(C0 + (size_t)gr * ldc + gc) = make_float2(v0, v1);
                } else if (mode == 4) {
                    *reinterpret_cast<float2*>(C0 + (size_t)gr * ldc + gc) = make_float2(v0, v1);
                } else if (mode == 1) {
                    const int which = (gc >= 1536) ? 2 : (gc >= 768 ? 1 : 0);
                    const int e = gc - which * 768;
                    const int h = e >> 6, d = e & 63;
                    const int bb = gr >> 10, s = gr & 1023;
                    u16 h0, l0, h1, l1;
                    splitHL(v0, h0, l0); splitHL(v1, h1, l1);
                    if (which < 2) {
                        u16* dh = which == 0 ? Q0h : Q1h;
                        u16* dl = which == 0 ? Q0l : Q1l;
                        const size_t base = (((size_t)(bb * HCFG + h)) * SCFG + s) * DCFG + d;
                        dh[base] = h0; dh[base + 1] = h1;
                        dl[base] = l0; dl[base + 1] = l1;
                    } else {
                        const size_t base = ((size_t)(bb * HCFG + h)) * DCFG * SCFG + (size_t)d * SCFG + s;
                        Q2h[base] = h0; Q2h[base + SCFG] = h1;
                        Q2l[base] = l0; Q2l[base + SCFG] = l1;
                    }
                } else if (mode == 2) {
                    const float g0 = 0.5f * v0 * (1.0f + erff(v0 * 0.70710678118654752f));
                    const float g1 = 0.5f * v1 * (1.0f + erff(v1 * 0.70710678118654752f));
                    u16 h0, l0, h1, l1;
                    splitHL(g0, h0, l0); splitHL(g1, h1, l1);
                    const size_t base = (size_t)gr * QMCFG + (size_t)gc * 4 + qi;
                    Q0h[base] = h0; Q0h[base + 4] = h1;
                    Q0l[base] = l0; Q0l[base + 4] = l1;
                } else {
                    u16 h0, l0, h1, l1;
                    splitHL(v0, h0, l0); splitHL(v1, h1, l1);
#pragma unroll
                    for (int qq = 0; qq < 4; ++qq) {
                        const int c0 = gc - qq, c1 = gc + 1 - qq;
                        const size_t sb = (size_t)qq * SLICESZ + (size_t)gr * 768;
                        if (c0 >= 0 && c0 < 768 && gc < colLimit)     { Q0h[sb + c0] = h0; Q0l[sb + c0] = l0; }
                        if (c1 >= 0 && c1 < 768 && gc + 1 < colLimit) { Q0h[sb + c1] = h1; Q0l[sb + c1] = l1; }
                    }
                }
            }
        }
    }
}
#define HM_SMEM_128 (2 * (128 * 144 + 128 * 144))
#define HM_SMEM_64  (2 * (64 * 144 + 128 * 144))

// ================= PV HMMA, fp16 2-seg (P split x V single), 2-stage =========
#define PV_STAGE_A 18432
#define PV_STAGE_B 9216
#define PV_SMEM (2 * (PV_STAGE_A + PV_STAGE_B))
__global__ void __launch_bounds__(256, 2) pv3(
    const u16* __restrict__ Phi, const u16* __restrict__ Plo,
    const u16* __restrict__ Vhi,
    u16* __restrict__ vh, u16* __restrict__ vl)
{
    extern __shared__ __align__(16) u16 sm[];
    const int t = threadIdx.x, lane = t & 31, wid = t >> 5;
    const int bh = blockIdx.y;
    const int rowBase = blockIdx.x * 128;
    const u16* Ahi = Phi + ((size_t)bh << 20);
    const u16* Alo = Plo + ((size_t)bh << 20);
    const u16* Bhi = Vhi + (size_t)bh * DCFG * SCFG;
    const int mBase = (wid >> 1) * 32, nBase = (wid & 1) * 32;
    float acc[2][4][4] = {};

    const int srow = t >> 1, half = t & 1;
    const size_t aRowOff = (size_t)(rowBase + srow) * SCFG + half * 32;
    const int srowB = (t & 127) >> 1;
    const size_t bRowOff = (size_t)srowB * SCFG + half * 32;
    const bool doB = t < 128;

    const uint32_t smb = smem_u32(sm);
    const uint32_t aBuf[2] = { smb, smb + PV_STAGE_A + PV_STAGE_B };
    const uint32_t bBuf[2] = { aBuf[0] + PV_STAGE_A, aBuf[1] + PV_STAGE_A };
    const uint32_t dstOffA = (uint32_t)(srow * 72 + half * 32) * 2;
    const uint32_t dstOffB = (uint32_t)(srowB * 72 + half * 32) * 2;

    const int mat = lane >> 3, lr8 = lane & 7;
    const int rOff = (mat & 1) * 8 + lr8;
    const int cByte = (mat >> 1) * 16;

    const int nk = SCFG >> 6;
    const int NIT = nk * 2;

#define PV_ISSUE(IT, BUF) do { \
    const int seg_ = (IT) / nk; \
    const int kb_ = ((IT) - seg_ * nk) * 64; \
    const u16* ap_ = (seg_ == 1 ? Alo : Ahi) + aRowOff + kb_; \
    const uint32_t ad_ = aBuf[BUF] + dstOffA; \
    _Pragma("unroll") \
    for (int j_ = 0; j_ < 4; ++j_) cp16(ad_ + j_ * 16, ap_ + j_ * 8); \
    if (doB) { \
        const u16* bp_ = Bhi + bRowOff + kb_; \
        const uint32_t bd_ = bBuf[BUF] + dstOffB; \
        _Pragma("unroll") \
        for (int j_ = 0; j_ < 4; ++j_) cp16(bd_ + j_ * 16, bp_ + j_ * 8); } \
    CP_COMMIT(); \
} while (0)

#define PV_COMPUTE(BUF) do { \
    _Pragma("unroll") \
    for (int s_ = 0; s_ < 4; ++s_) { \
        uint32_t bf_[4][2]; \
        _Pragma("unroll") \
        for (int bp_ = 0; bp_ < 2; ++bp_) { \
            uint32_t r4_[4]; \
            ldsm4(r4_, bBuf[BUF] + (uint32_t)((nBase + bp_ * 16 + rOff) * 144 + cByte + s_ * 32)); \
            bf_[2 * bp_][0] = r4_[0]; bf_[2 * bp_ + 1][0] = r4_[1]; \
            bf_[2 * bp_][1] = r4_[2]; bf_[2 * bp_ + 1][1] = r4_[3]; } \
        _Pragma("unroll") \
        for (int a_ = 0; a_ < 2; ++a_) { \
            uint32_t af_[4]; \
            ldsm4(af_, aBuf[BUF] + (uint32_t)((mBase + a_ * 16 + rOff) * 144 + cByte + s_ * 32)); \
            _Pragma("unroll") \
            for (int bn_ = 0; bn_ < 4; ++bn_) mma16816(acc[a_][bn_], af_, bf_[bn_]); } } \
} while (0)

    PV_ISSUE(0, 0);
    for (int it = 0; it < NIT; ++it) {
        CP_WAIT0();
        __syncthreads();
        if (it + 1 < NIT) PV_ISSUE(it + 1, (it + 1) & 1);
        PV_COMPUTE(it & 1);
    }

    const int b = bh / HCFG, h = bh % HCFG;
    const int r = lane >> 2, cp = (lane & 3) * 2;
#pragma unroll
    for (int a = 0; a < 2; ++a) {
#pragma unroll
        for (int bn = 0; bn < 4; ++bn) {
            const float* c = acc[a][bn];
            const int d = nBase + bn * 8 + cp;
#pragma unroll
            for (int hh = 0; hh < 2; ++hh) {
                const int s = rowBase + mBase + a * 16 + r + hh * 8;
                const size_t base = ((size_t)(b * SCFG + s)) * ECFG + h * DCFG + d;
                u16 h0, l0, h1, l1;
                splitHL(c[hh * 2], h0, l0); splitHL(c[hh * 2 + 1], h1, l1);
                vh[base] = h0; vh[base + 1] = h1;
                vl[base] = l0; vl[base + 1] = l1;
            }
        }
    }
}

// ---------------- row norms from planes ----------------
__global__ void norm_planes(const u16* __restrict__ sh, const u16* __restrict__ sl,
                            float* __restrict__ dst, int nrows) {
    const int r = blockIdx.x * blockDim.x + threadIdx.x;
    if (r >= nrows) return;
    const uint4* ph = reinterpret_cast<const uint4*>(sh + (size_t)r * DCFG);
    const uint4* pl = reinterpret_cast<const uint4*>(sl + (size_t)r * DCFG);
    float s = 0.f;
#pragma unroll
    for (int i = 0; i < 8; ++i) {
        uint4 th = ph[i], tl = pl[i];
        const uint32_t* wh = &th.x;
        const uint32_t* wl = &tl.x;
#pragma unroll
        for (int j = 0; j < 4; ++j) {
            float a = joinHL((u16)(wh[j] & 0xffffu), (u16)(wl[j] & 0xffffu));
            float b = joinHL((u16)(wh[j] >> 16),     (u16)(wl[j] >> 16));
            s += a * a + b * b;
        }
    }
    dst[r] = s;
}

// ---------------- softmax + RBF mix ----------------
__global__ void __launch_bounds__(256) mix_kernel(const float* __restrict__ P,
                                                  u16* __restrict__ Ph, u16* __restrict__ Pl,
                                                  const float* __restrict__ qn_,
                                                  const float* __restrict__ kn_,
                                                  const float* __restrict__ pond) {
    __shared__ float sbuf[34];
    const int row = blockIdx.x;
    const int bh  = row >> 10;
    const float* prow = P + (size_t)row * SCFG;
    const float* knb = kn_ + (size_t)bh * SCFG;
    const int tid = threadIdx.x;
    const float qn = qn_[row];
    const float sigma2 = fminf(fmaxf(qn, 1e-8f), 1e4f);

    float4 dt  = *reinterpret_cast<const float4*>(prow + tid * 4);
    float4 kn4 = *reinterpret_cast<const float4*>(knb + tid * 4);
    const float d[4]  = {dt.x, dt.y, dt.z, dt.w};
    const float kn[4] = {kn4.x, kn4.y, kn4.z, kn4.w};

    float lm = -1e30f;
#pragma unroll
    for (int u = 0; u < 4; ++u) lm = fmaxf(lm, d[u] * 0.125f);
    const float M = bred_max(lm, sbuf);

    float e[4], rb[4];
    float se = 0.f, sr = 0.f;
#pragma unroll
    for (int u = 0; u < 4; ++u) {
        e[u] = expf(d[u] * 0.125f - M);
        se += e[u];
        const float d2 = fmaxf(qn + kn[u] - 2.f * d[u], 0.f);
        rb[u] = expf(-d2 / sigma2);
        sr += rb[u];
    }
    const float Ls = bred_sum(se, sbuf);
    const float Lr = bred_sum(sr, sbuf);

    const float sv = 1.f / (1.f + expf(-pond[0]));
    const float p0 = 1.f - sv, p1 = sv;
    const float inv = 1.f / (p0 + p1 + 1e-7f);
    const float ca = p0 * inv / Ls;
    const float cb = p1 * inv / fmaxf(Lr, 1e-8f);

    u16 h[4], l[4];
#pragma unroll
    for (int u = 0; u < 4; ++u) splitHL(ca * e[u] + cb * rb[u], h[u], l[u]);
    uint2 ho, lo;
    ho.x = (uint32_t)h[0] | ((uint32_t)h[1] << 16);
    ho.y = (uint32_t)h[2] | ((uint32_t)h[3] << 16);
    lo.x = (uint32_t)l[0] | ((uint32_t)l[1] << 16);
    lo.y = (uint32_t)l[2] | ((uint32_t)l[3] << 16);
    *reinterpret_cast<uint2*>(Ph + (size_t)row * SCFG + tid * 4) = ho;
    *reinterpret_cast<uint2*>(Pl + (size_t)row * SCFG + tid * 4) = lo;
}

// ---------------- launch ----------------
extern "C" void kernel_launch(void* const* d_in, const int* in_sizes, int n_in,
                              void* d_out, int out_size) {
    const float* x     = (const float*)d_in[0];
    const float* ln1_w = (const float*)d_in[1];
    const float* ln1_b = (const float*)d_in[2];
    const float* Wq    = (const float*)d_in[3];
    const float* bq    = (const float*)d_in[4];
    const float* Wk    = (const float*)d_in[5];
    const float* bk    = (const float*)d_in[6];
    const float* Wv    = (const float*)d_in[7];
    const float* bv    = (const float*)d_in[8];
    const float* Wo    = (const float*)d_in[9];
    const float* bo    = (const float*)d_in[10];
    const float* pond  = (const float*)d_in[11];
    const float* ln2_w = (const float*)d_in[12];
    const float* ln2_b = (const float*)d_in[13];
    const float* fc1_W = (const float*)d_in[14];
    const float* fc1_b = (const float*)d_in[15];
    const float* vqc_W = (const float*)d_in[16];
    const float* vqc_b = (const float*)d_in[17];
    const float* fc2_W = (const float*)d_in[18];
    const float* fc2_b = (const float*)d_in[19];
    float* out = (float*)d_out;

    cudaFuncSetAttribute(hm3<128>, cudaFuncAttributeMaxDynamicSharedMemorySize, HM_SMEM_128);
    cudaFuncSetAttribute(hm3<64>,  cudaFuncAttributeMaxDynamicSharedMemorySize, HM_SMEM_64);
    cudaFuncSetAttribute(pv3, cudaFuncAttributeMaxDynamicSharedMemorySize, PV_SMEM);

    float *p_bqkv, *p_qn, *p_kn, *p_P, *p_x1;
    u16 *p_h_hi, *p_h_lo, *p_wq_hi, *p_wq_lo, *p_q_hi, *p_q_lo, *p_k_hi, *p_k_lo;
    u16 *p_vt_hi, *p_vt_lo, *p_P_hi, *p_P_lo, *p_va_hi, *p_va_lo, *p_wo_hi, *p_wo_lo;
    u16 *p_y_hi, *p_y_lo, *p_w1_hi, *p_w1_lo, *p_h1s_hi, *p_h1s_lo, *p_wv_hi, *p_wv_lo;
    u16 *p_z_hi, *p_z_lo, *p_w2_hi, *p_w2_lo;
    cudaGetSymbolAddress((void**)&p_bqkv, g_bqkv);
    cudaGetSymbolAddress((void**)&p_qn, g_qn);
    cudaGetSymbolAddress((void**)&p_kn, g_kn);
    cudaGetSymbolAddress((void**)&p_P, g_P);
    cudaGetSymbolAddress((void**)&p_x1, g_x1);
    cudaGetSymbolAddress((void**)&p_h_hi, g_h_hi);     cudaGetSymbolAddress((void**)&p_h_lo, g_h_lo);
    cudaGetSymbolAddress((void**)&p_wq_hi, g_wq_hi);   cudaGetSymbolAddress((void**)&p_wq_lo, g_wq_lo);
    cudaGetSymbolAddress((void**)&p_q_hi, g_q_hi);     cudaGetSymbolAddress((void**)&p_q_lo, g_q_lo);
    cudaGetSymbolAddress((void**)&p_k_hi, g_k_hi);     cudaGetSymbolAddress((void**)&p_k_lo, g_k_lo);
    cudaGetSymbolAddress((void**)&p_vt_hi, g_vt_hi);   cudaGetSymbolAddress((void**)&p_vt_lo, g_vt_lo);
    cudaGetSymbolAddress((void**)&p_P_hi, g_P_hi);     cudaGetSymbolAddress((void**)&p_P_lo, g_P_lo);
    cudaGetSymbolAddress((void**)&p_va_hi, g_va_hi);   cudaGetSymbolAddress((void**)&p_va_lo, g_va_lo);
    cudaGetSymbolAddress((void**)&p_wo_hi, g_wo_hi);   cudaGetSymbolAddress((void**)&p_wo_lo, g_wo_lo);
    cudaGetSymbolAddress((void**)&p_y_hi, g_y_hi);     cudaGetSymbolAddress((void**)&p_y_lo, g_y_lo);
    cudaGetSymbolAddress((void**)&p_w1_hi, g_w1_hi);   cudaGetSymbolAddress((void**)&p_w1_lo, g_w1_lo);
    cudaGetSymbolAddress((void**)&p_h1s_hi, g_h1s_hi); cudaGetSymbolAddress((void**)&p_h1s_lo, g_h1s_lo);
    cudaGetSymbolAddress((void**)&p_wv_hi, g_wv_hi);   cudaGetSymbolAddress((void**)&p_wv_lo, g_wv_lo);
    cudaGetSymbolAddress((void**)&p_z_hi, g_z_hi);     cudaGetSymbolAddress((void**)&p_z_lo, g_z_lo);
    cudaGetSymbolAddress((void**)&p_w2_hi, g_w2_hi);   cudaGetSymbolAddress((void**)&p_w2_lo, g_w2_lo);

    // 0) fused weight conversions + bias concat
    convAll<<<dim3(3, 896, 7), 256>>>(Wq, Wk, Wv, Wo, fc1_W, vqc_W, fc2_W);
    bcat_kernel<<<9, 256>>>(bq, bk, bv, p_bqkv);

    // 1) LN1 -> h planes
    ln_split<<<NTOK, 256>>>(x, ln1_w, ln1_b, p_h_hi, p_h_lo);

    // 2) fused QKV (2-seg: h split x W fp16)
    hm3<128><<<dim3(18, 16), 256, HM_SMEM_128>>>(p_h_hi, p_h_lo, ECFG, p_wq_hi, p_wq_lo, ECFG,
                                                 p_bqkv, nullptr, nullptr, 0,
                                                 p_q_hi, p_q_lo, p_k_hi, p_k_lo, p_vt_hi, p_vt_lo,
                                                 768, 1, 0, 2);

    // 3) norms
    norm_planes<<<(BHCFG * SCFG + 255) / 256, 256>>>(p_q_hi, p_q_lo, p_qn, BHCFG * SCFG);
    norm_planes<<<(BHCFG * SCFG + 255) / 256, 256>>>(p_k_hi, p_k_lo, p_kn, BHCFG * SCFG);

    // 4) logits (3-seg: near-exact, softmax-sensitive)
    hm3<128><<<dim3(8, 8, BHCFG), 256, HM_SMEM_128>>>(p_q_hi, p_q_lo, DCFG, p_k_hi, p_k_lo, DCFG,
                                                      nullptr, nullptr, p_P, SCFG,
                                                      nullptr, nullptr, nullptr, nullptr, nullptr, nullptr,
                                                      64, 4, 0, 3);

    // 5) softmax + RBF -> P planes
    mix_kernel<<<BHCFG * SCFG, 256>>>(p_P, p_P_hi, p_P_lo, p_qn, p_kn, pond);

    // 6) P @ V (2-seg: P split x V fp16)
    pv3<<<dim3(8, BHCFG), 256, PV_SMEM>>>(p_P_hi, p_P_lo, p_vt_hi, p_va_hi, p_va_lo);

    // 7) x1 = x + vals@Wo^T + bo (2-seg)
    hm3<64><<<dim3(6, 32), 256, HM_SMEM_64>>>(p_va_hi, p_va_lo, ECFG, p_wo_hi, p_wo_lo, ECFG,
                                              bo, x, p_x1, ECFG,
                                              nullptr, nullptr, nullptr, nullptr, nullptr, nullptr,
                                              768, 0, 0, 2);

    // 8) LN2 -> y planes
    ln_split<<<NTOK, 256>>>(p_x1, ln2_w, ln2_b, p_y_hi, p_y_lo);

    // 9) fc1 -> 4 pre-shifted h1 slices (2-seg)
    hm3<64><<<dim3(7, 32), 256, HM_SMEM_64>>>(p_y_hi, p_y_lo, ECFG, p_w1_hi, p_w1_lo, ECFG,
                                              fc1_b, nullptr, nullptr, 0,
                                              p_h1s_hi, p_h1s_lo, nullptr, nullptr, nullptr, nullptr,
                                              768, 3, H1C, 2);

    // 10) vqc + GELU -> z planes (2-seg)
    hm3<128><<<dim3(6, 16, 4), 256, HM_SMEM_128>>>(p_h1s_hi, p_h1s_lo, 768, p_wv_hi, p_wv_lo, ECFG,
                                                   vqc_b, nullptr, nullptr, 0,
                                                   p_z_hi, p_z_lo, nullptr, nullptr, nullptr, nullptr,
                                                   768, 2, 0, 2);

    // 11) out = x1 + z@fc2^T + fc2_b (2-seg)
    hm3<64><<<dim3(6, 32), 256, HM_SMEM_64>>>(p_z_hi, p_z_lo, QMCFG, p_w2_hi, p_w2_lo, QMCFG,
                                              fc2_b, p_x1, out, ECFG,
                                              nullptr, nullptr, nullptr, nullptr, nullptr, nullptr,
                                              3072, 0, 0, 2);

    (void)in_sizes; (void)n_in; (void)out_size;
}

// round 13
// speedup vs baseline: 2.2055x; 1.6347x over previous
#include <cuda_runtime.h>
#include <cuda_fp16.h>
#include <cstdint>
#include <math.h>

#define NTOK   2048
#define ECFG   768
#define SCFG   1024
#define HCFG   12
#define DCFG   64
#define BHCFG  24
#define QMCFG  3072
#define H1C    771
#define SLICESZ ((size_t)NTOK * 768)

typedef unsigned short u16;

// ---------------- scratch: fp16 planes (lo planes only where consumed) ------
__device__ __align__(16) u16 g_h_hi [NTOK * ECFG];
__device__ __align__(16) u16 g_wq_hi[(size_t)2304 * ECFG];
__device__ float g_bqkv[2304];
__device__ __align__(16) u16 g_q_hi [BHCFG * SCFG * DCFG];
__device__ __align__(16) u16 g_q_lo [BHCFG * SCFG * DCFG];   // logits seg1
__device__ __align__(16) u16 g_k_hi [BHCFG * SCFG * DCFG];
__device__ __align__(16) u16 g_k_lo [BHCFG * SCFG * DCFG];   // norms
__device__ __align__(16) u16 g_vt_hi[BHCFG * DCFG * SCFG];
__device__ float g_qn[BHCFG * SCFG];
__device__ float g_kn[BHCFG * SCFG];
__device__ float g_P [(size_t)BHCFG * SCFG * SCFG];
__device__ __align__(16) u16 g_P_hi[(size_t)BHCFG * SCFG * SCFG];
__device__ __align__(16) u16 g_va_hi[NTOK * ECFG];
__device__ __align__(16) u16 g_wo_hi[(size_t)ECFG * ECFG];
__device__ float g_x1[NTOK * ECFG];
__device__ __align__(16) u16 g_y_hi [NTOK * ECFG];
__device__ __align__(16) u16 g_w1_hi[(size_t)896 * ECFG];
__device__ __align__(16) u16 g_h1s_hi[4 * SLICESZ];
__device__ __align__(16) u16 g_wv_hi[(size_t)ECFG * ECFG];
__device__ __align__(16) u16 g_z_hi [(size_t)NTOK * QMCFG];
__device__ __align__(16) u16 g_w2_hi[(size_t)ECFG * QMCFG];

// ---------------- helpers ----------------
__device__ __forceinline__ uint32_t smem_u32(const void* p) {
    uint32_t a;
    asm("{ .reg .u64 t; cvta.to.shared.u64 t, %1; cvt.u32.u64 %0, t; }" : "=r"(a) : "l"(p));
    return a;
}
__device__ __forceinline__ u16 toH(float x) { return __half_as_ushort(__float2half_rn(x)); }
__device__ __forceinline__ void splitHL(float x, u16& h, u16& l) {
    __half hh = __float2half_rn(x);
    __half ll = __float2half_rn(x - __half2float(hh));
    h = __half_as_ushort(hh);
    l = __half_as_ushort(ll);
}
__device__ __forceinline__ float joinHL(u16 h, u16 l) {
    return __half2float(__ushort_as_half(h)) + __half2float(__ushort_as_half(l));
}
__device__ __forceinline__ void ldsm4(uint32_t* r, uint32_t addr) {
    asm volatile("ldmatrix.sync.aligned.m8n8.x4.shared.b16 {%0,%1,%2,%3}, [%4];"
        : "=r"(r[0]), "=r"(r[1]), "=r"(r[2]), "=r"(r[3]) : "r"(addr));
}
__device__ __forceinline__ void mma16816(float* c, const uint32_t* a, const uint32_t* b) {
    asm volatile("mma.sync.aligned.m16n8k16.row.col.f32.f16.f16.f32 "
        "{%0,%1,%2,%3}, {%4,%5,%6,%7}, {%8,%9}, {%0,%1,%2,%3};"
        : "+f"(c[0]), "+f"(c[1]), "+f"(c[2]), "+f"(c[3])
        : "r"(a[0]), "r"(a[1]), "r"(a[2]), "r"(a[3]), "r"(b[0]), "r"(b[1]));
}
__device__ __forceinline__ void cp16(uint32_t dst, const void* src) {
    asm volatile("cp.async.cg.shared.global [%0], [%1], 16;" :: "r"(dst), "l"(src));
}
#define CP_COMMIT() asm volatile("cp.async.commit_group;" ::: "memory")
#define CP_WAIT0()  asm volatile("cp.async.wait_group 0;" ::: "memory")

// ---------------- fused weight conversion (hi plane only) ----------------
__global__ void __launch_bounds__(256) convAll(
    const float* __restrict__ Wq, const float* __restrict__ Wk, const float* __restrict__ Wv,
    const float* __restrict__ Wo, const float* __restrict__ W1, const float* __restrict__ Wvq,
    const float* __restrict__ W2)
{
    const int job = blockIdx.z;
    const int r = blockIdx.y;
    const int k0 = blockIdx.x * 256 + threadIdx.x;
    const float* src; u16 *dh;
    int Kc = 768, rows = 768, inRows = 768;
    switch (job) {
        case 0: src = Wq;  dh = g_wq_hi;                      break;
        case 1: src = Wk;  dh = g_wq_hi + (size_t)768 * 768;  break;
        case 2: src = Wv;  dh = g_wq_hi + (size_t)1536 * 768; break;
        case 3: src = Wo;  dh = g_wo_hi; break;
        case 4: src = W1;  dh = g_w1_hi; rows = 896; inRows = H1C; break;
        case 5: src = Wvq; dh = g_wv_hi; break;
        default: src = W2; dh = g_w2_hi; Kc = 3072; break;
    }
    if (r >= rows || k0 >= 768) return;
#pragma unroll 4
    for (int j = 0; j < 4; ++j) {
        const int k = k0 + j * 768;
        if (k >= Kc) break;
        float v = (r < inRows) ? src[(size_t)r * Kc + k] : 0.f;
        dh[(size_t)r * Kc + k] = toH(v);
    }
}

__global__ void bcat_kernel(const float* __restrict__ a, const float* __restrict__ b,
                            const float* __restrict__ c, float* __restrict__ o) {
    int t = blockIdx.x * 256 + threadIdx.x;
    if (t < 768) o[t] = a[t];
    else if (t < 1536) o[t] = b[t - 768];
    else if (t < 2304) o[t] = c[t - 1536];
}

// ---------------- block reductions ----------------
__device__ __forceinline__ float bred_sum(float v, float* sbuf) {
#pragma unroll
    for (int o = 16; o > 0; o >>= 1) v += __shfl_xor_sync(0xffffffffu, v, o);
    int w = threadIdx.x >> 5, l = threadIdx.x & 31;
    __syncthreads();
    if (l == 0) sbuf[w] = v;
    __syncthreads();
    if (threadIdx.x < 32) {
        float t = (l < 8) ? sbuf[l] : 0.f;
#pragma unroll
        for (int o = 4; o > 0; o >>= 1) t += __shfl_xor_sync(0xffffffffu, t, o);
        if (l == 0) sbuf[32] = t;
    }
    __syncthreads();
    return sbuf[32];
}
__device__ __forceinline__ float bred_max(float v, float* sbuf) {
#pragma unroll
    for (int o = 16; o > 0; o >>= 1) v = fmaxf(v, __shfl_xor_sync(0xffffffffu, v, o));
    int w = threadIdx.x >> 5, l = threadIdx.x & 31;
    __syncthreads();
    if (l == 0) sbuf[w] = v;
    __syncthreads();
    if (threadIdx.x < 32) {
        float t = (l < 8) ? sbuf[l] : -1e30f;
#pragma unroll
        for (int o = 4; o > 0; o >>= 1) t = fmaxf(t, __shfl_xor_sync(0xffffffffu, t, o));
        if (l == 0) sbuf[32] = t;
    }
    __syncthreads();
    return sbuf[32];
}

// ---------------- layernorm -> hi plane ----------------
__global__ void __launch_bounds__(256) ln_split(const float* __restrict__ x,
                                                const float* __restrict__ w,
                                                const float* __restrict__ b,
                                                u16* __restrict__ oh) {
    __shared__ float sbuf[34];
    const int row = blockIdx.x;
    const float* xr = x + (size_t)row * ECFG;
    float v[3];
    float s = 0.f, sq = 0.f;
#pragma unroll
    for (int u = 0; u < 3; ++u) {
        v[u] = xr[threadIdx.x + u * 256];
        s += v[u];
        sq += v[u] * v[u];
    }
    s  = bred_sum(s, sbuf);
    sq = bred_sum(sq, sbuf);
    const float mean = s * (1.0f / ECFG);
    const float inv  = rsqrtf(sq * (1.0f / ECFG) - mean * mean + 1e-5f);
#pragma unroll
    for (int u = 0; u < 3; ++u) {
        int e = threadIdx.x + u * 256;
        oh[(size_t)row * ECFG + e] = toH((v[u] - mean) * inv * w[e] + b[e]);
    }
}

// ================= HMMA GEMM, fp16, 2-stage cp.async, TM templated ====
// nseg=1: Ah.Bh          (dense: both single fp16)
// nseg=2: + Al.Bh        (logits: q exact-split x k single)
// mode 0: C0 = acc + bias (+resid), fp32
// mode 1: QKV -> q hi/lo Q0, k hi/lo Q1 [bh][s][d]; v transposed hi Q2 [bh][d][s]
// mode 2: vqc: A = slice qi of h1s; +bias, GELU -> z hi [gr*3072+gc*4+qi]
// mode 3: fc1: +bias -> 4 shifted h1 hi slices, gc < colLimit
// mode 4: logits: A,B offset z*65536, C0 offset z<<20, raw fp32
template <int TM>
__global__ void __launch_bounds__(256, 2) hm3(
    const u16* __restrict__ Ahi, const u16* __restrict__ Alo, int ldA,
    const u16* __restrict__ Bhi, int ldB,
    const float* __restrict__ bias, const float* __restrict__ resid,
    float* __restrict__ C0, int ldc,
    u16* __restrict__ Q0h, u16* __restrict__ Q0l,
    u16* __restrict__ Q1h, u16* __restrict__ Q1l,
    u16* __restrict__ Q2h,
    int Kc, int mode, int colLimit, int nseg)
{
    constexpr int AF = (TM == 128) ? 4 : 2;
    constexpr int A_STAGE = TM * 144;
    constexpr int B_STAGE = 128 * 144;
    constexpr int STAGE = A_STAGE + B_STAGE;
    extern __shared__ __align__(16) u16 sm[];
    const int t = threadIdx.x, lane = t & 31, wid = t >> 5;
    const int rowBase = blockIdx.y * TM, colBase = blockIdx.x * 128, qi = blockIdx.z;
    if (mode == 2) { Ahi += (size_t)qi * SLICESZ; }
    if (mode == 4) {
        Ahi += (size_t)qi << 16; Alo += (size_t)qi << 16;
        Bhi += (size_t)qi << 16;
        C0  += (size_t)qi << 20;
    }
    const int mBase = (wid >> 2) * (AF * 16), nBase = (wid & 3) * 32;
    float acc[AF][4][4] = {};

    int srowA, colWA, nCpA;
    if (TM == 128) { srowA = t >> 1; colWA = (t & 1) * 32; nCpA = 4; }
    else           { srowA = t >> 2; colWA = (t & 3) * 16; nCpA = 2; }
    const int srowB = t >> 1;
    const int colWB = (t & 1) * 32;
    const size_t aRowOff = (size_t)(rowBase + srowA) * ldA + colWA;
    const size_t bRowOff = (size_t)(colBase + srowB) * ldB + colWB;
    const uint32_t smb = smem_u32(sm);
    const uint32_t aBuf[2] = { smb,            smb + STAGE };
    const uint32_t bBuf[2] = { smb + A_STAGE,  smb + STAGE + A_STAGE };
    const uint32_t dstOffA = (uint32_t)(srowA * 144 + colWA * 2);
    const uint32_t dstOffB = (uint32_t)(srowB * 144 + colWB * 2);

    const int mat = lane >> 3, lr8 = lane & 7;
    const int rOff = (mat & 1) * 8 + lr8;
    const int cByte = (mat >> 1) * 16;

    const int nk = Kc >> 6;
    const int NIT = nk * nseg;

#define HM_ISSUE(IT, BUF) do { \
    const int seg_ = (IT) / nk; \
    const int kb_ = ((IT) - seg_ * nk) * 64; \
    const u16* ap_ = (seg_ == 1 ? Alo : Ahi) + aRowOff + kb_; \
    const u16* bp_ = Bhi + bRowOff + kb_; \
    const uint32_t ad_ = aBuf[BUF] + dstOffA; \
    const uint32_t bd_ = bBuf[BUF] + dstOffB; \
    _Pragma("unroll") \
    for (int j_ = 0; j_ < nCpA; ++j_) cp16(ad_ + j_ * 16, ap_ + j_ * 8); \
    _Pragma("unroll") \
    for (int j_ = 0; j_ < 4; ++j_) cp16(bd_ + j_ * 16, bp_ + j_ * 8); \
    CP_COMMIT(); \
} while (0)

#define HM_COMPUTE(BUF) do { \
    _Pragma("unroll") \
    for (int s_ = 0; s_ < 4; ++s_) { \
        uint32_t bf_[4][2]; \
        _Pragma("unroll") \
        for (int bp_ = 0; bp_ < 2; ++bp_) { \
            uint32_t r4_[4]; \
            ldsm4(r4_, bBuf[BUF] + (uint32_t)((nBase + bp_ * 16 + rOff) * 144 + cByte + s_ * 32)); \
            bf_[2 * bp_][0] = r4_[0]; bf_[2 * bp_ + 1][0] = r4_[1]; \
            bf_[2 * bp_][1] = r4_[2]; bf_[2 * bp_ + 1][1] = r4_[3]; } \
        _Pragma("unroll") \
        for (int a_ = 0; a_ < AF; ++a_) { \
            uint32_t af_[4]; \
            ldsm4(af_, aBuf[BUF] + (uint32_t)((mBase + a_ * 16 + rOff) * 144 + cByte + s_ * 32)); \
            _Pragma("unroll") \
            for (int bn_ = 0; bn_ < 4; ++bn_) mma16816(acc[a_][bn_], af_, bf_[bn_]); } } \
} while (0)

    HM_ISSUE(0, 0);
    for (int it = 0; it < NIT; ++it) {
        CP_WAIT0();
        __syncthreads();
        if (it + 1 < NIT) HM_ISSUE(it + 1, (it + 1) & 1);
        HM_COMPUTE(it & 1);
    }

    // ---------------- epilogue ----------------
    const int r = lane >> 2, cp = (lane & 3) * 2;
#pragma unroll
    for (int a = 0; a < AF; ++a) {
#pragma unroll
        for (int bn = 0; bn < 4; ++bn) {
            const float* c = acc[a][bn];
            const int gc = colBase + nBase + bn * 8 + cp;
            const float b0 = bias ? bias[gc] : 0.f;
            const float b1 = bias ? bias[gc + 1] : 0.f;
#pragma unroll
            for (int hh = 0; hh < 2; ++hh) {
                const int gr = rowBase + mBase + a * 16 + r + hh * 8;
                float v0 = c[hh * 2] + b0, v1 = c[hh * 2 + 1] + b1;
                if (mode == 0) {
                    if (resid) {
                        v0 += resid[(size_t)gr * ldc + gc];
                        v1 += resid[(size_t)gr * ldc + gc + 1];
                    }
                    *reinterpret_cast<float2*>(C0 + (size_t)gr * ldc + gc) = make_float2(v0, v1);
                } else if (mode == 4) {
                    *reinterpret_cast<float2*>(C0 + (size_t)gr * ldc + gc) = make_float2(v0, v1);
                } else if (mode == 1) {
                    const int which = (gc >= 1536) ? 2 : (gc >= 768 ? 1 : 0);
                    const int e = gc - which * 768;
                    const int h = e >> 6, d = e & 63;
                    const int bb = gr >> 10, s = gr & 1023;
                    if (which < 2) {
                        u16 h0, l0, h1, l1;
                        splitHL(v0, h0, l0); splitHL(v1, h1, l1);
                        u16* dh = which == 0 ? Q0h : Q1h;
                        u16* dl = which == 0 ? Q0l : Q1l;
                        const size_t base = (((size_t)(bb * HCFG + h)) * SCFG + s) * DCFG + d;
                        dh[base] = h0; dh[base + 1] = h1;
                        dl[base] = l0; dl[base + 1] = l1;
                    } else {
                        const size_t base = ((size_t)(bb * HCFG + h)) * DCFG * SCFG + (size_t)d * SCFG + s;
                        Q2h[base] = toH(v0); Q2h[base + SCFG] = toH(v1);
                    }
                } else if (mode == 2) {
                    const float g0 = 0.5f * v0 * (1.0f + erff(v0 * 0.70710678118654752f));
                    const float g1 = 0.5f * v1 * (1.0f + erff(v1 * 0.70710678118654752f));
                    const size_t base = (size_t)gr * QMCFG + (size_t)gc * 4 + qi;
                    Q0h[base] = toH(g0); Q0h[base + 4] = toH(g1);
                } else {
                    const u16 h0 = toH(v0), h1 = toH(v1);
#pragma unroll
                    for (int qq = 0; qq < 4; ++qq) {
                        const int c0 = gc - qq, c1 = gc + 1 - qq;
                        const size_t sb = (size_t)qq * SLICESZ + (size_t)gr * 768;
                        if (c0 >= 0 && c0 < 768 && gc < colLimit)     Q0h[sb + c0] = h0;
                        if (c1 >= 0 && c1 < 768 && gc + 1 < colLimit) Q0h[sb + c1] = h1;
                    }
                }
            }
        }
    }
}
#define HM_SMEM_128 (2 * (128 * 144 + 128 * 144))
#define HM_SMEM_64  (2 * (64 * 144 + 128 * 144))

// ================= PV HMMA, fp16 1-seg, 2-stage =========
#define PV_STAGE_A 18432
#define PV_STAGE_B 9216
#define PV_SMEM (2 * (PV_STAGE_A + PV_STAGE_B))
__global__ void __launch_bounds__(256, 2) pv3(
    const u16* __restrict__ Phi,
    const u16* __restrict__ Vhi,
    u16* __restrict__ vh)
{
    extern __shared__ __align__(16) u16 sm[];
    const int t = threadIdx.x, lane = t & 31, wid = t >> 5;
    const int bh = blockIdx.y;
    const int rowBase = blockIdx.x * 128;
    const u16* Ahi = Phi + ((size_t)bh << 20);
    const u16* Bhi = Vhi + (size_t)bh * DCFG * SCFG;
    const int mBase = (wid >> 1) * 32, nBase = (wid & 1) * 32;
    float acc[2][4][4] = {};

    const int srow = t >> 1, half = t & 1;
    const size_t aRowOff = (size_t)(rowBase + srow) * SCFG + half * 32;
    const int srowB = (t & 127) >> 1;
    const size_t bRowOff = (size_t)srowB * SCFG + half * 32;
    const bool doB = t < 128;

    const uint32_t smb = smem_u32(sm);
    const uint32_t aBuf[2] = { smb, smb + PV_STAGE_A + PV_STAGE_B };
    const uint32_t bBuf[2] = { aBuf[0] + PV_STAGE_A, aBuf[1] + PV_STAGE_A };
    const uint32_t dstOffA = (uint32_t)(srow * 72 + half * 32) * 2;
    const uint32_t dstOffB = (uint32_t)(srowB * 72 + half * 32) * 2;

    const int mat = lane >> 3, lr8 = lane & 7;
    const int rOff = (mat & 1) * 8 + lr8;
    const int cByte = (mat >> 1) * 16;

    const int NIT = SCFG >> 6;   // 16

#define PV_ISSUE(IT, BUF) do { \
    const int kb_ = (IT) * 64; \
    const u16* ap_ = Ahi + aRowOff + kb_; \
    const uint32_t ad_ = aBuf[BUF] + dstOffA; \
    _Pragma("unroll") \
    for (int j_ = 0; j_ < 4; ++j_) cp16(ad_ + j_ * 16, ap_ + j_ * 8); \
    if (doB) { \
        const u16* bp_ = Bhi + bRowOff + kb_; \
        const uint32_t bd_ = bBuf[BUF] + dstOffB; \
        _Pragma("unroll") \
        for (int j_ = 0; j_ < 4; ++j_) cp16(bd_ + j_ * 16, bp_ + j_ * 8); } \
    CP_COMMIT(); \
} while (0)

#define PV_COMPUTE(BUF) do { \
    _Pragma("unroll") \
    for (int s_ = 0; s_ < 4; ++s_) { \
        uint32_t bf_[4][2]; \
        _Pragma("unroll") \
        for (int bp_ = 0; bp_ < 2; ++bp_) { \
            uint32_t r4_[4]; \
            ldsm4(r4_, bBuf[BUF] + (uint32_t)((nBase + bp_ * 16 + rOff) * 144 + cByte + s_ * 32)); \
            bf_[2 * bp_][0] = r4_[0]; bf_[2 * bp_ + 1][0] = r4_[1]; \
            bf_[2 * bp_][1] = r4_[2]; bf_[2 * bp_ + 1][1] = r4_[3]; } \
        _Pragma("unroll") \
        for (int a_ = 0; a_ < 2; ++a_) { \
            uint32_t af_[4]; \
            ldsm4(af_, aBuf[BUF] + (uint32_t)((mBase + a_ * 16 + rOff) * 144 + cByte + s_ * 32)); \
            _Pragma("unroll") \
            for (int bn_ = 0; bn_ < 4; ++bn_) mma16816(acc[a_][bn_], af_, bf_[bn_]); } } \
} while (0)

    PV_ISSUE(0, 0);
    for (int it = 0; it < NIT; ++it) {
        CP_WAIT0();
        __syncthreads();
        if (it + 1 < NIT) PV_ISSUE(it + 1, (it + 1) & 1);
        PV_COMPUTE(it & 1);
    }

    const int b = bh / HCFG, h = bh % HCFG;
    const int r = lane >> 2, cp = (lane & 3) * 2;
#pragma unroll
    for (int a = 0; a < 2; ++a) {
#pragma unroll
        for (int bn = 0; bn < 4; ++bn) {
            const float* c = acc[a][bn];
            const int d = nBase + bn * 8 + cp;
#pragma unroll
            for (int hh = 0; hh < 2; ++hh) {
                const int s = rowBase + mBase + a * 16 + r + hh * 8;
                const size_t base = ((size_t)(b * SCFG + s)) * ECFG + h * DCFG + d;
                vh[base] = toH(c[hh * 2]);
                vh[base + 1] = toH(c[hh * 2 + 1]);
            }
        }
    }
}

// ---------------- row norms from hi/lo planes ----------------
__global__ void norm_planes(const u16* __restrict__ sh, const u16* __restrict__ sl,
                            float* __restrict__ dst, int nrows) {
    const int r = blockIdx.x * blockDim.x + threadIdx.x;
    if (r >= nrows) return;
    const uint4* ph = reinterpret_cast<const uint4*>(sh + (size_t)r * DCFG);
    const uint4* pl = reinterpret_cast<const uint4*>(sl + (size_t)r * DCFG);
    float s = 0.f;
#pragma unroll
    for (int i = 0; i < 8; ++i) {
        uint4 th = ph[i], tl = pl[i];
        const uint32_t* wh = &th.x;
        const uint32_t* wl = &tl.x;
#pragma unroll
        for (int j = 0; j < 4; ++j) {
            float a = joinHL((u16)(wh[j] & 0xffffu), (u16)(wl[j] & 0xffffu));
            float b = joinHL((u16)(wh[j] >> 16),     (u16)(wl[j] >> 16));
            s += a * a + b * b;
        }
    }
    dst[r] = s;
}

// ---------------- softmax + RBF mix -> hi plane ----------------
__global__ void __launch_bounds__(256) mix_kernel(const float* __restrict__ P,
                                                  u16* __restrict__ Ph,
                                                  const float* __restrict__ qn_,
                                                  const float* __restrict__ kn_,
                                                  const float* __restrict__ pond) {
    __shared__ float sbuf[34];
    const int row = blockIdx.x;
    const int bh  = row >> 10;
    const float* prow = P + (size_t)row * SCFG;
    const float* knb = kn_ + (size_t)bh * SCFG;
    const int tid = threadIdx.x;
    const float qn = qn_[row];
    const float sigma2 = fminf(fmaxf(qn, 1e-8f), 1e4f);

    float4 dt  = *reinterpret_cast<const float4*>(prow + tid * 4);
    float4 kn4 = *reinterpret_cast<const float4*>(knb + tid * 4);
    const float d[4]  = {dt.x, dt.y, dt.z, dt.w};
    const float kn[4] = {kn4.x, kn4.y, kn4.z, kn4.w};

    float lm = -1e30f;
#pragma unroll
    for (int u = 0; u < 4; ++u) lm = fmaxf(lm, d[u] * 0.125f);
    const float M = bred_max(lm, sbuf);

    float e[4], rb[4];
    float se = 0.f, sr = 0.f;
#pragma unroll
    for (int u = 0; u < 4; ++u) {
        e[u] = expf(d[u] * 0.125f - M);
        se += e[u];
        const float d2 = fmaxf(qn + kn[u] - 2.f * d[u], 0.f);
        rb[u] = expf(-d2 / sigma2);
        sr += rb[u];
    }
    const float Ls = bred_sum(se, sbuf);
    const float Lr = bred_sum(sr, sbuf);

    const float sv = 1.f / (1.f + expf(-pond[0]));
    const float p0 = 1.f - sv, p1 = sv;
    const float inv = 1.f / (p0 + p1 + 1e-7f);
    const float ca = p0 * inv / Ls;
    const float cb = p1 * inv / fmaxf(Lr, 1e-8f);

    uint2 ho;
    ho.x = (uint32_t)toH(ca * e[0] + cb * rb[0]) | ((uint32_t)toH(ca * e[1] + cb * rb[1]) << 16);
    ho.y = (uint32_t)toH(ca * e[2] + cb * rb[2]) | ((uint32_t)toH(ca * e[3] + cb * rb[3]) << 16);
    *reinterpret_cast<uint2*>(Ph + (size_t)row * SCFG + tid * 4) = ho;
}

// ---------------- launch ----------------
extern "C" void kernel_launch(void* const* d_in, const int* in_sizes, int n_in,
                              void* d_out, int out_size) {
    const float* x     = (const float*)d_in[0];
    const float* ln1_w = (const float*)d_in[1];
    const float* ln1_b = (const float*)d_in[2];
    const float* Wq    = (const float*)d_in[3];
    const float* bq    = (const float*)d_in[4];
    const float* Wk    = (const float*)d_in[5];
    const float* bk    = (const float*)d_in[6];
    const float* Wv    = (const float*)d_in[7];
    const float* bv    = (const float*)d_in[8];
    const float* Wo    = (const float*)d_in[9];
    const float* bo    = (const float*)d_in[10];
    const float* pond  = (const float*)d_in[11];
    const float* ln2_w = (const float*)d_in[12];
    const float* ln2_b = (const float*)d_in[13];
    const float* fc1_W = (const float*)d_in[14];
    const float* fc1_b = (const float*)d_in[15];
    const float* vqc_W = (const float*)d_in[16];
    const float* vqc_b = (const float*)d_in[17];
    const float* fc2_W = (const float*)d_in[18];
    const float* fc2_b = (const float*)d_in[19];
    float* out = (float*)d_out;

    cudaFuncSetAttribute(hm3<128>, cudaFuncAttributeMaxDynamicSharedMemorySize, HM_SMEM_128);
    cudaFuncSetAttribute(hm3<64>,  cudaFuncAttributeMaxDynamicSharedMemorySize, HM_SMEM_64);
    cudaFuncSetAttribute(pv3, cudaFuncAttributeMaxDynamicSharedMemorySize, PV_SMEM);

    float *p_bqkv, *p_qn, *p_kn, *p_P, *p_x1;
    u16 *p_h_hi, *p_wq_hi, *p_q_hi, *p_q_lo, *p_k_hi, *p_k_lo;
    u16 *p_vt_hi, *p_P_hi, *p_va_hi, *p_wo_hi;
    u16 *p_y_hi, *p_w1_hi, *p_h1s_hi, *p_wv_hi, *p_z_hi, *p_w2_hi;
    cudaGetSymbolAddress((void**)&p_bqkv, g_bqkv);
    cudaGetSymbolAddress((void**)&p_qn, g_qn);
    cudaGetSymbolAddress((void**)&p_kn, g_kn);
    cudaGetSymbolAddress((void**)&p_P, g_P);
    cudaGetSymbolAddress((void**)&p_x1, g_x1);
    cudaGetSymbolAddress((void**)&p_h_hi, g_h_hi);
    cudaGetSymbolAddress((void**)&p_wq_hi, g_wq_hi);
    cudaGetSymbolAddress((void**)&p_q_hi, g_q_hi);
    cudaGetSymbolAddress((void**)&p_q_lo, g_q_lo);
    cudaGetSymbolAddress((void**)&p_k_hi, g_k_hi);
    cudaGetSymbolAddress((void**)&p_k_lo, g_k_lo);
    cudaGetSymbolAddress((void**)&p_vt_hi, g_vt_hi);
    cudaGetSymbolAddress((void**)&p_P_hi, g_P_hi);
    cudaGetSymbolAddress((void**)&p_va_hi, g_va_hi);
    cudaGetSymbolAddress((void**)&p_wo_hi, g_wo_hi);
    cudaGetSymbolAddress((void**)&p_y_hi, g_y_hi);
    cudaGetSymbolAddress((void**)&p_w1_hi, g_w1_hi);
    cudaGetSymbolAddress((void**)&p_h1s_hi, g_h1s_hi);
    cudaGetSymbolAddress((void**)&p_wv_hi, g_wv_hi);
    cudaGetSymbolAddress((void**)&p_z_hi, g_z_hi);
    cudaGetSymbolAddress((void**)&p_w2_hi, g_w2_hi);

    // 0) fused weight conversions + bias concat
    convAll<<<dim3(3, 896, 7), 256>>>(Wq, Wk, Wv, Wo, fc1_W, vqc_W, fc2_W);
    bcat_kernel<<<9, 256>>>(bq, bk, bv, p_bqkv);

    // 1) LN1 -> h hi
    ln_split<<<NTOK, 256>>>(x, ln1_w, ln1_b, p_h_hi);

    // 2) fused QKV (1-seg)
    hm3<128><<<dim3(18, 16), 256, HM_SMEM_128>>>(p_h_hi, p_h_hi, ECFG, p_wq_hi, ECFG,
                                                 p_bqkv, nullptr, nullptr, 0,
                                                 p_q_hi, p_q_lo, p_k_hi, p_k_lo, p_vt_hi,
                                                 768, 1, 0, 1);

    // 3) norms (exact from hi+lo planes)
    norm_planes<<<(BHCFG * SCFG + 255) / 256, 256>>>(p_q_hi, p_q_lo, p_qn, BHCFG * SCFG);
    norm_planes<<<(BHCFG * SCFG + 255) / 256, 256>>>(p_k_hi, p_k_lo, p_kn, BHCFG * SCFG);

    // 4) logits (2-seg: q exact-split x k single)
    hm3<128><<<dim3(8, 8, BHCFG), 256, HM_SMEM_128>>>(p_q_hi, p_q_lo, DCFG, p_k_hi, DCFG,
                                                      nullptr, nullptr, p_P, SCFG,
                                                      nullptr, nullptr, nullptr, nullptr, nullptr,
                                                      64, 4, 0, 2);

    // 5) softmax + RBF -> P hi
    mix_kernel<<<BHCFG * SCFG, 256>>>(p_P, p_P_hi, p_qn, p_kn, pond);

    // 6) P @ V (1-seg)
    pv3<<<dim3(8, BHCFG), 256, PV_SMEM>>>(p_P_hi, p_vt_hi, p_va_hi);

    // 7) x1 = x + vals@Wo^T + bo (1-seg)
    hm3<64><<<dim3(6, 32), 256, HM_SMEM_64>>>(p_va_hi, p_va_hi, ECFG, p_wo_hi, ECFG,
                                              bo, x, p_x1, ECFG,
                                              nullptr, nullptr, nullptr, nullptr, nullptr,
                                              768, 0, 0, 1);

    // 8) LN2 -> y hi
    ln_split<<<NTOK, 256>>>(p_x1, ln2_w, ln2_b, p_y_hi);

    // 9) fc1 -> 4 pre-shifted h1 hi slices (1-seg)
    hm3<64><<<dim3(7, 32), 256, HM_SMEM_64>>>(p_y_hi, p_y_hi, ECFG, p_w1_hi, ECFG,
                                              fc1_b, nullptr, nullptr, 0,
                                              p_h1s_hi, nullptr, nullptr, nullptr, nullptr,
                                              768, 3, H1C, 1);

    // 10) vqc + GELU -> z hi (1-seg)
    hm3<128><<<dim3(6, 16, 4), 256, HM_SMEM_128>>>(p_h1s_hi, p_h1s_hi, 768, p_wv_hi, ECFG,
                                                   vqc_b, nullptr, nullptr, 0,
                                                   p_z_hi, nullptr, nullptr, nullptr, nullptr,
                                                   768, 2, 0, 1);

    // 11) out = x1 + z@fc2^T + fc2_b (1-seg)
    hm3<64><<<dim3(6, 32), 256, HM_SMEM_64>>>(p_z_hi, p_z_hi, QMCFG, p_w2_hi, QMCFG,
                                              fc2_b, p_x1, out, ECFG,
                                              nullptr, nullptr, nullptr, nullptr, nullptr,
                                              3072, 0, 0, 1);

    (void)in_sizes; (void)n_in; (void)out_size;
}